// round 1
// baseline (speedup 1.0000x reference)
#include <cuda_runtime.h>
#include <cuda_bf16.h>

#define NROWS 8000
#define CDIM  256
#define HW    1600
#define BM    64
#define BN    64
#define KB    32

// ---------------- device scratch (no allocations allowed) ----------------
__device__ __align__(16) float g_memory[NROWS * CDIM]; // gathered memory matrix [8000,256]
__device__ float g_memlab[NROWS];                       // memory labels (float)
__device__ float g_pos[NROWS];                          // pos[i] = dot(f1,f2)*10
__device__ float g_alf1[NROWS];                         // anchor labels as float
__device__ float g_alf2[NROWS];
__device__ float g_L[2][NROWS];                         // per-row -log(logits+eps)

// ---------------- prep: gather memory matrix + memory labels ----------------
__global__ void prep_gather(const float* __restrict__ ul1, const float* __restrict__ ul2,
                            const int* __restrict__ sel1, const int* __restrict__ sel2,
                            const int* __restrict__ pl1, const int* __restrict__ pl2) {
    int j = blockIdx.x;        // memory row 0..7999
    int c = threadIdx.x;       // channel 0..255
    int n;
    const float* ul;
    const int* pl;
    if (j < 4000) { n = sel1[j];        ul = ul1; pl = pl1; }
    else          { n = sel2[j - 4000]; ul = ul2; pl = pl2; }
    int b = n / HW;
    int hw = n - b * HW;
    // ul layout [B, C, H, W]: element (b, c, h, w) at ((b*C + c)*HW + hw)
    g_memory[j * CDIM + c] = ul[(b * CDIM + c) * HW + hw];
    if (c == 0) g_memlab[j] = (float)pl[n];
}

// ---------------- prep: pos[i] = dot(feat1[i], feat2[i]) * 10 ----------------
__global__ void prep_pos(const float* __restrict__ f1, const float* __restrict__ f2) {
    int warp = threadIdx.x >> 5;
    int lane = threadIdx.x & 31;
    int i = blockIdx.x * 8 + warp;
    const float4* a = (const float4*)(f1 + i * CDIM);
    const float4* b = (const float4*)(f2 + i * CDIM);
    float s = 0.f;
    #pragma unroll
    for (int q = lane; q < CDIM / 4; q += 32) {
        float4 x = a[q], y = b[q];
        s += x.x * y.x + x.y * y.y + x.z * y.z + x.w * y.w;
    }
    #pragma unroll
    for (int off = 16; off > 0; off >>= 1)
        s += __shfl_xor_sync(0xffffffffu, s, off);
    if (lane == 0) g_pos[i] = s * 10.f;
}

// ---------------- prep: label int -> float ----------------
__global__ void prep_labels(const int* __restrict__ pl1, const int* __restrict__ pl2) {
    int i = blockIdx.x * blockDim.x + threadIdx.x;
    if (i < NROWS) {
        g_alf1[i] = (float)pl1[i];
        g_alf2[i] = (float)pl2[i];
    }
}

// ---------------- main fused GEMM + masked softmax denominators ----------------
// grid (125, 2): blockIdx.x = row stripe (64 rows), blockIdx.y = anchor (0: feat1, 1: feat2)
// 256 threads, 16x16 layout, 4x4 micro-tile, double-buffered K staging.
#define STAGE_STORE(s)                                                                 \
    do {                                                                               \
        const float4 a0 = *(const float4*)(A + (rowBase + trow) * CDIM + kt_ld + t8);  \
        const float4 a1 = *(const float4*)(A + (rowBase + trow + 32) * CDIM + kt_ld + t8); \
        const float4 b0 = *(const float4*)(g_memory + (jt + trow) * CDIM + kt_ld + t8);    \
        const float4 b1 = *(const float4*)(g_memory + (jt + trow + 32) * CDIM + kt_ld + t8); \
        a_s[s][t8 + 0][trow] = a0.x; a_s[s][t8 + 1][trow] = a0.y;                      \
        a_s[s][t8 + 2][trow] = a0.z; a_s[s][t8 + 3][trow] = a0.w;                      \
        a_s[s][t8 + 0][trow + 32] = a1.x; a_s[s][t8 + 1][trow + 32] = a1.y;            \
        a_s[s][t8 + 2][trow + 32] = a1.z; a_s[s][t8 + 3][trow + 32] = a1.w;            \
        b_s[s][t8 + 0][trow] = b0.x; b_s[s][t8 + 1][trow] = b0.y;                      \
        b_s[s][t8 + 2][trow] = b0.z; b_s[s][t8 + 3][trow] = b0.w;                      \
        b_s[s][t8 + 0][trow + 32] = b1.x; b_s[s][t8 + 1][trow + 32] = b1.y;            \
        b_s[s][t8 + 2][trow + 32] = b1.z; b_s[s][t8 + 3][trow + 32] = b1.w;            \
    } while (0)

__global__ __launch_bounds__(256) void contrast_main(const float* __restrict__ feat1,
                                                     const float* __restrict__ feat2) {
    __shared__ float a_s[2][KB][BM + 4];   // [k][row], +4 pad keeps 16B alignment, no conflicts
    __shared__ float b_s[2][KB][BN + 4];   // [k][col]
    __shared__ float al_s[BN];

    const int tid = threadIdx.x;
    const int tx = tid & 15, ty = tid >> 4;
    const int anchor = blockIdx.y;
    const float* __restrict__ A = anchor ? feat2 : feat1;
    const float* __restrict__ alf = anchor ? g_alf2 : g_alf1;
    const int rowBase = blockIdx.x * BM;

    const int t8 = (tid & 7) * 4;   // k quad within stage
    const int trow = tid >> 3;      // 0..31

    float rmax[4], tall[4], t1a[4];
    #pragma unroll
    for (int r = 0; r < 4; r++) { rmax[r] = -1e30f; tall[r] = 0.f; t1a[r] = 0.f; }

    for (int jt = 0; jt < NROWS; jt += BN) {
        float acc[4][4];
        #pragma unroll
        for (int r = 0; r < 4; r++)
            #pragma unroll
            for (int c = 0; c < 4; c++) acc[r][c] = 0.f;

        {   // prologue: stage 0
            int kt_ld = 0;
            STAGE_STORE(0);
        }
        if (tid < BN) al_s[tid] = alf[jt + tid];
        __syncthreads();

        #pragma unroll
        for (int kt = 0; kt < CDIM; kt += KB) {
            const int cur = (kt / KB) & 1;
            if (kt + KB < CDIM) {
                int kt_ld = kt + KB;
                STAGE_STORE(cur ^ 1);
            }
            #pragma unroll
            for (int kk = 0; kk < KB; kk++) {
                const float4 a4 = *(const float4*)&a_s[cur][kk][ty * 4];
                const float4 b4 = *(const float4*)&b_s[cur][kk][tx * 4];
                acc[0][0] = fmaf(a4.x, b4.x, acc[0][0]);
                acc[0][1] = fmaf(a4.x, b4.y, acc[0][1]);
                acc[0][2] = fmaf(a4.x, b4.z, acc[0][2]);
                acc[0][3] = fmaf(a4.x, b4.w, acc[0][3]);
                acc[1][0] = fmaf(a4.y, b4.x, acc[1][0]);
                acc[1][1] = fmaf(a4.y, b4.y, acc[1][1]);
                acc[1][2] = fmaf(a4.y, b4.z, acc[1][2]);
                acc[1][3] = fmaf(a4.y, b4.w, acc[1][3]);
                acc[2][0] = fmaf(a4.z, b4.x, acc[2][0]);
                acc[2][1] = fmaf(a4.z, b4.y, acc[2][1]);
                acc[2][2] = fmaf(a4.z, b4.z, acc[2][2]);
                acc[2][3] = fmaf(a4.z, b4.w, acc[2][3]);
                acc[3][0] = fmaf(a4.w, b4.x, acc[3][0]);
                acc[3][1] = fmaf(a4.w, b4.y, acc[3][1]);
                acc[3][2] = fmaf(a4.w, b4.z, acc[3][2]);
                acc[3][3] = fmaf(a4.w, b4.w, acc[3][3]);
            }
            __syncthreads();
        }

        // epilogue: fold tile into per-row running (max, sumexp_all, sumexp_label1)
        // fixed shift 12 is an upper bound on S = dot*10 (|dot| <= 1), so exp never overflows
        #pragma unroll
        for (int r = 0; r < 4; r++) {
            #pragma unroll
            for (int c = 0; c < 4; c++) {
                float s = acc[r][c];
                rmax[r] = fmaxf(rmax[r], s);
                float e = __expf(fmaf(s, 10.f, -12.f));
                tall[r] += e;
                t1a[r] = fmaf(e, al_s[tx * 4 + c], t1a[r]);
            }
        }
        __syncthreads();  // protect al_s before next tile overwrites
    }

    // cross-thread reduction: each row's partials live in the 16 lanes sharing ty
    #pragma unroll
    for (int r = 0; r < 4; r++) {
        #pragma unroll
        for (int off = 8; off > 0; off >>= 1) {
            rmax[r] = fmaxf(rmax[r], __shfl_xor_sync(0xffffffffu, rmax[r], off));
            tall[r] += __shfl_xor_sync(0xffffffffu, tall[r], off);
            t1a[r] += __shfl_xor_sync(0xffffffffu, t1a[r], off);
        }
    }
    if (tx == 0) {
        #pragma unroll
        for (int r = 0; r < 4; r++) {
            int i = rowBase + ty * 4 + r;
            float posv = g_pos[i];
            float mfull = fmaxf(rmax[r] * 10.f, posv);   // reference max includes pos column
            float t1v = t1a[r];
            // weight(i,j) = (anchor_label[j] != memory_label[i])
            float tsel = (g_memlab[i] == 0.f) ? t1v : (tall[r] - t1v);
            float epos = __expf(posv - mfull);
            float sum = epos + tsel * __expf(12.f - mfull);
            float logits = epos / (sum + 1e-8f);
            g_L[anchor][i] = -logf(logits + 1e-8f);
        }
    }
}

// ---------------- deterministic final reduction ----------------
__global__ void finalize(const float* __restrict__ plog1, const float* __restrict__ plog2,
                         float* __restrict__ out) {
    __shared__ float sm[256][4];
    int tid = threadIdx.x;
    float n1 = 0.f, c1 = 0.f, n2 = 0.f, c2 = 0.f;
    for (int i = tid; i < NROWS; i += 256) {
        float q1 = plog1[i], q2 = plog2[i];
        if (q2 > 0.7f && q1 < q2) { n1 += g_L[0][i]; c1 += 1.f; }
        if (q1 > 0.7f && q2 < q1) { n2 += g_L[1][i]; c2 += 1.f; }
    }
    sm[tid][0] = n1; sm[tid][1] = c1; sm[tid][2] = n2; sm[tid][3] = c2;
    __syncthreads();
    for (int s = 128; s > 0; s >>= 1) {
        if (tid < s) {
            #pragma unroll
            for (int q = 0; q < 4; q++) sm[tid][q] += sm[tid + s][q];
        }
        __syncthreads();
    }
    if (tid == 0)
        out[0] = sm[0][0] / (sm[0][1] + 1e-12f) + sm[0][2] / (sm[0][3] + 1e-12f);
}

// ---------------- launch ----------------
extern "C" void kernel_launch(void* const* d_in, const int* in_sizes, int n_in,
                              void* d_out, int out_size) {
    const float* feat1 = (const float*)d_in[0];
    const float* feat2 = (const float*)d_in[1];
    const float* ul1   = (const float*)d_in[2];
    const float* ul2   = (const float*)d_in[3];
    const int*   pl1   = (const int*)d_in[4];
    const int*   pl2   = (const int*)d_in[5];
    const float* plog1 = (const float*)d_in[6];
    const float* plog2 = (const float*)d_in[7];
    const int*   sel1  = (const int*)d_in[8];
    const int*   sel2  = (const int*)d_in[9];
    float* out = (float*)d_out;

    prep_gather<<<NROWS, 256>>>(ul1, ul2, sel1, sel2, pl1, pl2);
    prep_pos<<<NROWS / 8, 256>>>(feat1, feat2);
    prep_labels<<<(NROWS + 255) / 256, 256>>>(pl1, pl2);
    contrast_main<<<dim3(NROWS / BM, 2), 256>>>(feat1, feat2);
    finalize<<<1, 256>>>(plog1, plog2, out);
}

// round 3
// speedup vs baseline: 4.3696x; 4.3696x over previous
#include <cuda_runtime.h>
#include <cuda_bf16.h>

#define NROWS 8000
#define CDIM  256
#define HW    1600
#define MT    128
#define NT    64
#define MTILES 63
#define NCHUNK 125
#define NSTAGE 250
#define ATILE_BYTES  131072   // 128 rows x 256 k x 2B x (hi+lo), fragment-tiled
#define BSTAGE_BYTES 32768    // 64 cols x 128 k x 2B x (hi+lo), fragment-tiled

// ---- dynamic smem map ----
#define SM_AF   0             // A-full barrier
#define SM_FULL 16            // full[s] at +16*s
#define SM_FREE 48            // free[s] at +16*s
#define SM_A    1024          // 131072
#define SM_B    132096        // 2 x 32768
#define SMEM_TOTAL 197632

// ---------------- device scratch ----------------
__device__ __align__(1024) unsigned char g_Asw[2][(size_t)MTILES * ATILE_BYTES];
__device__ __align__(1024) unsigned char g_Bsw[(size_t)NSTAGE * BSTAGE_BYTES];
__device__ float g_memlab[NROWS];
__device__ float g_pos[NROWS];
__device__ float g_alf[2][NROWS];
__device__ float g_L[2][NROWS];

// ---------------- PTX helpers ----------------
__device__ __forceinline__ unsigned elect_one_pred() {
    unsigned pred;
    asm volatile("{\n\t.reg .pred p;\n\telect.sync _|p, 0xFFFFFFFF;\n\tselp.b32 %0, 1, 0, p;\n\t}"
                 : "=r"(pred));
    return pred;
}
__device__ __forceinline__ unsigned smem_u32(const void* p) {
    unsigned a;
    asm("{ .reg .u64 t; cvta.to.shared.u64 t, %1; cvt.u32.u64 %0, t; }" : "=r"(a) : "l"(p));
    return a;
}
#define MBAR_INIT(addr, cnt) \
    asm volatile("mbarrier.init.shared.b64 [%0], %1;" :: "r"(addr), "r"(cnt) : "memory")
#define MBAR_EXPECT_TX(addr, bytes) \
    asm volatile("mbarrier.arrive.expect_tx.shared.b64 _, [%0], %1;" :: "r"(addr), "r"(bytes) : "memory")
#define MBAR_ARRIVE(addr) \
    asm volatile("mbarrier.arrive.shared.b64 _, [%0];" :: "r"(addr) : "memory")
#define MBAR_WAIT(addr, ph) do { \
    unsigned _m = (addr), _p = (ph), _d; \
    asm volatile("{\n\t.reg .pred p;\n\tmbarrier.try_wait.parity.acquire.cta.shared::cta.b64 p, [%1], %2;\n\tselp.b32 %0, 1, 0, p;\n\t}" \
                 : "=r"(_d) : "r"(_m), "r"(_p) : "memory"); \
    if (!_d) { \
        asm volatile("{\n\t.reg .pred P1;\n\tWL%=:\n\tmbarrier.try_wait.parity.acquire.cta.shared::cta.b64 P1, [%0], %1, 0x989680;\n\t@P1 bra.uni WD%=;\n\tbra.uni WL%=;\n\tWD%=:\n\t}" \
                     :: "r"(_m), "r"(_p) : "memory"); \
    } } while (0)
#define BULK_G2S(dst, src, bytes, mbar) \
    asm volatile("cp.async.bulk.shared::cluster.global.mbarrier::complete_tx::bytes [%0], [%1], %2, [%3];" \
                 :: "r"(dst), "l"(src), "r"(bytes), "r"(mbar) : "memory")
#define LDSM4(r, addr) \
    asm volatile("ldmatrix.sync.aligned.m8n8.x4.shared.b16 {%0,%1,%2,%3}, [%4];" \
                 : "=r"((r)[0]), "=r"((r)[1]), "=r"((r)[2]), "=r"((r)[3]) : "r"(addr))
#define MMA_BF16(c, a, b0, b1) \
    asm volatile("mma.sync.aligned.m16n8k16.row.col.f32.bf16.bf16.f32 " \
                 "{%0,%1,%2,%3}, {%4,%5,%6,%7}, {%8,%9}, {%0,%1,%2,%3};" \
                 : "+f"((c)[0]), "+f"((c)[1]), "+f"((c)[2]), "+f"((c)[3]) \
                 : "r"((a)[0]), "r"((a)[1]), "r"((a)[2]), "r"((a)[3]), "r"(b0), "r"(b1))

// ---------------- prep: feats -> fragment-tiled bf16 hi/lo A tiles ----------------
// A tile layout (per anchor,mtile, version): blocks (kt 0..15, mt 0..7) of 512B,
// block = 4x 8x8 matrices (128B each) in ldmatrix.x4 A order.
__global__ void prep_feat(const float* __restrict__ f1, const float* __restrict__ f2) {
    int i = blockIdx.x, a = blockIdx.y, c = threadIdx.x;   // i < 8064 (pad -> 0)
    const float* f = a ? f2 : f1;
    float x = (i < NROWS) ? f[i * CDIM + c] : 0.f;
    __nv_bfloat16 hi = __float2bfloat16(x);
    __nv_bfloat16 lo = __float2bfloat16(x - __bfloat162float(hi));
    int tile = i >> 7, m = i & 127;
    int mt = m >> 4, mi8 = (m >> 3) & 1, mr = m & 7;
    int kt = c >> 4, kin = c & 15, kh = kin >> 3, kc = kin & 7;
    int q = kh * 2 + mi8;   // a0=(m0-7,k0-7) a1=(m8-15,k0-7) a2=(m0-7,k8-15) a3
    unsigned off = (unsigned)(((kt * 8 + mt) << 9) + (q << 7) + (mr << 4) + (kc << 1));
    unsigned char* base = g_Asw[a] + (size_t)tile * ATILE_BYTES;
    *(__nv_bfloat16*)(base + off) = hi;
    *(__nv_bfloat16*)(base + 65536 + off) = lo;
}

// ---------------- prep: gather memory rows -> fragment-tiled bf16 hi/lo B stages ----------------
// Stage (chunk t, khalf h): blocks (kt 0..7, nt2 0..3) of 512B, x4 B order.
__global__ void prep_gather(const float* __restrict__ ul1, const float* __restrict__ ul2,
                            const int* __restrict__ sel1, const int* __restrict__ sel2,
                            const int* __restrict__ pl1, const int* __restrict__ pl2) {
    int j = blockIdx.x, c = threadIdx.x;
    int n; const float* ul; const int* pl;
    if (j < 4000) { n = sel1[j];        ul = ul1; pl = pl1; }
    else          { n = sel2[j - 4000]; ul = ul2; pl = pl2; }
    int b = n / HW, hw = n - b * HW;
    float x = ul[(b * CDIM + c) * HW + hw];
    __nv_bfloat16 hi = __float2bfloat16(x);
    __nv_bfloat16 lo = __float2bfloat16(x - __bfloat162float(hi));
    int chunk = j >> 6, nn = j & 63;
    int h = c >> 7, k7 = c & 127;
    int kt = k7 >> 4, k16 = k7 & 15, kh = k16 >> 3, kc = k16 & 7;
    int nt2 = nn >> 4, ni8 = (nn >> 3) & 1, nr = nn & 7;
    int q = ni8 * 2 + kh;   // b order: (n0-7,k0-7)(n0-7,k8-15)(n8-15,k0-7)(n8-15,k8-15)
    unsigned off = (unsigned)(((kt * 4 + nt2) << 9) + (q << 7) + (nr << 4) + (kc << 1));
    unsigned char* base = g_Bsw + (size_t)(chunk * 2 + h) * BSTAGE_BYTES;
    *(__nv_bfloat16*)(base + off) = hi;
    *(__nv_bfloat16*)(base + 16384 + off) = lo;
    if (c == 0) g_memlab[j] = (float)pl[n];
}

// ---------------- prep: pos[i] = dot(feat1[i], feat2[i]) * 10 (exact fp32) ----------------
__global__ void prep_pos(const float* __restrict__ f1, const float* __restrict__ f2) {
    int warp = threadIdx.x >> 5, lane = threadIdx.x & 31;
    int i = blockIdx.x * 8 + warp;
    const float4* a = (const float4*)(f1 + i * CDIM);
    const float4* b = (const float4*)(f2 + i * CDIM);
    float s = 0.f;
    #pragma unroll
    for (int q = lane; q < CDIM / 4; q += 32) {
        float4 x = a[q], y = b[q];
        s += x.x * y.x + x.y * y.y + x.z * y.z + x.w * y.w;
    }
    #pragma unroll
    for (int off = 16; off > 0; off >>= 1) s += __shfl_xor_sync(0xffffffffu, s, off);
    if (lane == 0) g_pos[i] = s * 10.f;
}

__global__ void prep_labels(const int* __restrict__ pl1, const int* __restrict__ pl2) {
    int i = blockIdx.x * blockDim.x + threadIdx.x;
    if (i < NROWS) { g_alf[0][i] = (float)pl1[i]; g_alf[1][i] = (float)pl2[i]; }
}

// ---------------- main: mma.sync bf16 3-pass GEMM + fused masked softmax stats ----------------
// grid (63, 2), 288 threads: warps 0-7 = MMA consumers (4M x 2N, warp tile 32x32),
// warp 8 = bulk-copy producer.
__global__ __launch_bounds__(288, 1) void contrast_mm() {
    extern __shared__ char smem[];
    const unsigned sb = smem_u32(smem);
    const int tid = threadIdx.x, wid = tid >> 5, lane = tid & 31;
    const int mtile = blockIdx.x, anchor = blockIdx.y;

    if (tid == 0) {
        MBAR_INIT(sb + SM_AF, 1);
        MBAR_INIT(sb + SM_FULL + 0, 1);  MBAR_INIT(sb + SM_FULL + 16, 1);
        MBAR_INIT(sb + SM_FREE + 0, 8);  MBAR_INIT(sb + SM_FREE + 16, 8);
    }
    __syncthreads();

    if (wid < 8) {
        // -------- consumer --------
        const int wm = wid >> 1, wn = wid & 1;
        const unsigned lanoff = (unsigned)(((lane >> 3) << 7) + ((lane & 7) << 4));
        const unsigned abase = sb + SM_A + lanoff;
        const float* __restrict__ labf = g_alf[anchor];

        float C[2][4][4];
        #pragma unroll
        for (int mi = 0; mi < 2; mi++)
            #pragma unroll
            for (int nj = 0; nj < 4; nj++)
                #pragma unroll
                for (int e = 0; e < 4; e++) C[mi][nj][e] = 0.f;
        float rmx[2][2], tal[2][2], t1a[2][2];
        #pragma unroll
        for (int mi = 0; mi < 2; mi++)
            #pragma unroll
            for (int rh = 0; rh < 2; rh++) { rmx[mi][rh] = -1e30f; tal[mi][rh] = 0.f; t1a[mi][rh] = 0.f; }

        MBAR_WAIT(sb + SM_AF, 0);   // A tile resident

        for (int sIdx = 0; sIdx < NSTAGE; sIdx++) {
            const int buf = sIdx & 1;                 // == k-half h
            MBAR_WAIT(sb + SM_FULL + 16 * buf, (sIdx >> 1) & 1);
            const unsigned bbase = sb + SM_B + (buf << 15) + lanoff;
            const int ktg0 = buf * 8;
            #pragma unroll
            for (int kt = 0; kt < 8; kt++) {
                unsigned Ah[2][4], Al[2][4], Bh[2][4], Bl[2][4];
                #pragma unroll
                for (int mi = 0; mi < 2; mi++) {
                    unsigned ablk = abase + (unsigned)(((ktg0 + kt) * 8 + wm * 2 + mi) << 9);
                    LDSM4(Ah[mi], ablk);
                    LDSM4(Al[mi], ablk + 65536);
                }
                #pragma unroll
                for (int bj = 0; bj < 2; bj++) {
                    unsigned bblk = bbase + (unsigned)((kt * 4 + wn * 2 + bj) << 9);
                    LDSM4(Bh[bj], bblk);
                    LDSM4(Bl[bj], bblk + 16384);
                }
                #pragma unroll
                for (int mi = 0; mi < 2; mi++)
                    #pragma unroll
                    for (int nj = 0; nj < 4; nj++) {
                        const int bj = nj >> 1, s2 = (nj & 1) * 2;
                        MMA_BF16(C[mi][nj], Ah[mi], Bh[bj][s2], Bh[bj][s2 + 1]);
                        MMA_BF16(C[mi][nj], Ah[mi], Bl[bj][s2], Bl[bj][s2 + 1]);
                        MMA_BF16(C[mi][nj], Al[mi], Bh[bj][s2], Bh[bj][s2 + 1]);
                    }
            }
            if (lane == 0) MBAR_ARRIVE(sb + SM_FREE + 16 * buf);

            if (buf) {  // chunk complete: fold stats, reset C
                const int cb = (sIdx >> 1) * NT + wn * 32 + ((lane & 3) << 1);
                float l0[4], l1[4];
                #pragma unroll
                for (int nj = 0; nj < 4; nj++) {
                    l0[nj] = labf[cb + nj * 8];
                    l1[nj] = labf[cb + nj * 8 + 1];
                }
                #pragma unroll
                for (int mi = 0; mi < 2; mi++)
                    #pragma unroll
                    for (int nj = 0; nj < 4; nj++)
                        #pragma unroll
                        for (int e = 0; e < 4; e++) {
                            const int rh = e >> 1;
                            float s = C[mi][nj][e];
                            rmx[mi][rh] = fmaxf(rmx[mi][rh], s);
                            float ex = __expf(fmaf(s, 10.f, -12.f));
                            tal[mi][rh] += ex;
                            t1a[mi][rh] = fmaf(ex, (e & 1) ? l1[nj] : l0[nj], t1a[mi][rh]);
                            C[mi][nj][e] = 0.f;
                        }
            }
        }

        // quad reduce (lanes sharing a row differ in lane&3)
        #pragma unroll
        for (int mi = 0; mi < 2; mi++)
            #pragma unroll
            for (int rh = 0; rh < 2; rh++) {
                #pragma unroll
                for (int off = 1; off <= 2; off <<= 1) {
                    rmx[mi][rh] = fmaxf(rmx[mi][rh], __shfl_xor_sync(0xffffffffu, rmx[mi][rh], off));
                    tal[mi][rh] += __shfl_xor_sync(0xffffffffu, tal[mi][rh], off);
                    t1a[mi][rh] += __shfl_xor_sync(0xffffffffu, t1a[mi][rh], off);
                }
            }
        __syncthreads();   // all warps done reading A before stats overwrite it
        if ((lane & 3) == 0) {
            float* sred = (float*)(smem + SM_A);
            #pragma unroll
            for (int mi = 0; mi < 2; mi++)
                #pragma unroll
                for (int rh = 0; rh < 2; rh++) {
                    int r = wm * 32 + mi * 16 + rh * 8 + (lane >> 2);
                    float* p = sred + (wn * 128 + r) * 4;
                    p[0] = rmx[mi][rh]; p[1] = tal[mi][rh]; p[2] = t1a[mi][rh];
                }
        }
    } else {
        // -------- producer --------
        if (elect_one_pred()) {
            MBAR_EXPECT_TX(sb + SM_AF, ATILE_BYTES);
            BULK_G2S(sb + SM_A, g_Asw[anchor] + (size_t)mtile * ATILE_BYTES,
                     (unsigned)ATILE_BYTES, sb + SM_AF);
            for (int sIdx = 0; sIdx < NSTAGE; sIdx++) {
                const int buf = sIdx & 1;
                if (sIdx >= 2) MBAR_WAIT(sb + SM_FREE + 16 * buf, ((sIdx - 2) >> 1) & 1);
                MBAR_EXPECT_TX(sb + SM_FULL + 16 * buf, BSTAGE_BYTES);
                BULK_G2S(sb + SM_B + (buf << 15), g_Bsw + (size_t)sIdx * BSTAGE_BYTES,
                         (unsigned)BSTAGE_BYTES, sb + SM_FULL + 16 * buf);
            }
        }
        __syncthreads();   // matches consumers' pre-stats barrier
    }

    __syncthreads();
    if (tid < 128) {
        const float* sred = (const float*)(smem + SM_A);
        const float* p0 = sred + tid * 4;
        const float* p1 = sred + (128 + tid) * 4;
        float rmax = fmaxf(p0[0], p1[0]);
        float tall = p0[1] + p1[1];
        float t1v  = p0[2] + p1[2];
        const int i = mtile * MT + tid;
        if (i < NROWS) {
            float posv = g_pos[i];
            float mfull = fmaxf(rmax * 10.f, posv);
            float tsel = (g_memlab[i] == 0.f) ? t1v : (tall - t1v);
            float epos = __expf(posv - mfull);
            float sum = epos + tsel * __expf(12.f - mfull);
            g_L[anchor][i] = -logf(epos / (sum + 1e-8f) + 1e-8f);
        }
    }
}

// ---------------- deterministic final reduction ----------------
__global__ void finalize(const float* __restrict__ plog1, const float* __restrict__ plog2,
                         float* __restrict__ out) {
    __shared__ float sm[256][4];
    int tid = threadIdx.x;
    float n1 = 0.f, c1 = 0.f, n2 = 0.f, c2 = 0.f;
    for (int i = tid; i < NROWS; i += 256) {
        float q1 = plog1[i], q2 = plog2[i];
        if (q2 > 0.7f && q1 < q2) { n1 += g_L[0][i]; c1 += 1.f; }
        if (q1 > 0.7f && q2 < q1) { n2 += g_L[1][i]; c2 += 1.f; }
    }
    sm[tid][0] = n1; sm[tid][1] = c1; sm[tid][2] = n2; sm[tid][3] = c2;
    __syncthreads();
    for (int s = 128; s > 0; s >>= 1) {
        if (tid < s) {
            #pragma unroll
            for (int q = 0; q < 4; q++) sm[tid][q] += sm[tid + s][q];
        }
        __syncthreads();
    }
    if (tid == 0)
        out[0] = sm[0][0] / (sm[0][1] + 1e-12f) + sm[0][2] / (sm[0][3] + 1e-12f);
}

// ---------------- launch ----------------
extern "C" void kernel_launch(void* const* d_in, const int* in_sizes, int n_in,
                              void* d_out, int out_size) {
    const float* feat1 = (const float*)d_in[0];
    const float* feat2 = (const float*)d_in[1];
    const float* ul1   = (const float*)d_in[2];
    const float* ul2   = (const float*)d_in[3];
    const int*   pl1   = (const int*)d_in[4];
    const int*   pl2   = (const int*)d_in[5];
    const float* plog1 = (const float*)d_in[6];
    const float* plog2 = (const float*)d_in[7];
    const int*   sel1  = (const int*)d_in[8];
    const int*   sel2  = (const int*)d_in[9];
    float* out = (float*)d_out;

    cudaFuncSetAttribute(contrast_mm, cudaFuncAttributeMaxDynamicSharedMemorySize, SMEM_TOTAL);

    prep_feat<<<dim3(MTILES * MT, 2), 256>>>(feat1, feat2);
    prep_gather<<<NROWS, 256>>>(ul1, ul2, sel1, sel2, pl1, pl2);
    prep_pos<<<NROWS / 8, 256>>>(feat1, feat2);
    prep_labels<<<(NROWS + 255) / 256, 256>>>(pl1, pl2);
    contrast_mm<<<dim3(MTILES, 2), 288, SMEM_TOTAL>>>();
    finalize<<<1, 256>>>(plog1, plog2, out);
}

// round 4
// speedup vs baseline: 9.7084x; 2.2218x over previous
#include <cuda_runtime.h>
#include <cuda_fp16.h>

#define NROWS 8000
#define NPAD  8064
#define CDIM  256
#define HW    1600
#define MT    128
#define MTILES 63
#define NSTAGE 63
#define ATILE_BYTES  65536    // 128 rows x 256 k x 2B fp16 hi, fragment-tiled
#define BSTAGE_BYTES 65536    // 128 cols x 256 k x 2B fp16 hi, fragment-tiled

// ---- dynamic smem map ----
#define SM_AF   0             // A-full barrier
#define SM_FULL 16            // full[s] at +16*s
#define SM_FREE 48            // free[s] at +16*s
#define SM_A    1024          // 65536
#define SM_B    66560         // 2 x 65536
#define SMEM_TOTAL 197632

// ---------------- device scratch ----------------
__device__ __align__(1024) unsigned char g_Asw[2][(size_t)MTILES * ATILE_BYTES];
__device__ __align__(1024) unsigned char g_Bsw[(size_t)NSTAGE * BSTAGE_BYTES];
__device__ float g_memlab[NROWS];
__device__ float g_pos[NROWS];
__device__ float g_alf[2][NPAD];
__device__ float g_L[2][NROWS];

// ---------------- PTX helpers ----------------
__device__ __forceinline__ unsigned elect_one_pred() {
    unsigned pred;
    asm volatile("{\n\t.reg .pred p;\n\telect.sync _|p, 0xFFFFFFFF;\n\tselp.b32 %0, 1, 0, p;\n\t}"
                 : "=r"(pred));
    return pred;
}
__device__ __forceinline__ unsigned smem_u32(const void* p) {
    unsigned a;
    asm("{ .reg .u64 t; cvta.to.shared.u64 t, %1; cvt.u32.u64 %0, t; }" : "=r"(a) : "l"(p));
    return a;
}
#define MBAR_INIT(addr, cnt) \
    asm volatile("mbarrier.init.shared.b64 [%0], %1;" :: "r"(addr), "r"(cnt) : "memory")
#define MBAR_EXPECT_TX(addr, bytes) \
    asm volatile("mbarrier.arrive.expect_tx.shared.b64 _, [%0], %1;" :: "r"(addr), "r"(bytes) : "memory")
#define MBAR_ARRIVE(addr) \
    asm volatile("mbarrier.arrive.shared.b64 _, [%0];" :: "r"(addr) : "memory")
#define MBAR_WAIT(addr, ph) do { \
    unsigned _m = (addr), _p = (ph), _d; \
    asm volatile("{\n\t.reg .pred p;\n\tmbarrier.try_wait.parity.acquire.cta.shared::cta.b64 p, [%1], %2;\n\tselp.b32 %0, 1, 0, p;\n\t}" \
                 : "=r"(_d) : "r"(_m), "r"(_p) : "memory"); \
    if (!_d) { \
        asm volatile("{\n\t.reg .pred P1;\n\tWL%=:\n\tmbarrier.try_wait.parity.acquire.cta.shared::cta.b64 P1, [%0], %1, 0x989680;\n\t@P1 bra.uni WD%=;\n\tbra.uni WL%=;\n\tWD%=:\n\t}" \
                     :: "r"(_m), "r"(_p) : "memory"); \
    } } while (0)
#define BULK_G2S(dst, src, bytes, mbar) \
    asm volatile("cp.async.bulk.shared::cluster.global.mbarrier::complete_tx::bytes [%0], [%1], %2, [%3];" \
                 :: "r"(dst), "l"(src), "r"(bytes), "r"(mbar) : "memory")
#define LDSM4(r, addr) \
    asm volatile("ldmatrix.sync.aligned.m8n8.x4.shared.b16 {%0,%1,%2,%3}, [%4];" \
                 : "=r"((r)[0]), "=r"((r)[1]), "=r"((r)[2]), "=r"((r)[3]) : "r"(addr))
#define MMA_FP16(c, a, b0, b1) \
    asm volatile("mma.sync.aligned.m16n8k16.row.col.f32.f16.f16.f32 " \
                 "{%0,%1,%2,%3}, {%4,%5,%6,%7}, {%8,%9}, {%0,%1,%2,%3};" \
                 : "+f"((c)[0]), "+f"((c)[1]), "+f"((c)[2]), "+f"((c)[3]) \
                 : "r"((a)[0]), "r"((a)[1]), "r"((a)[2]), "r"((a)[3]), "r"(b0), "r"(b1))

// ---------------- prep: feats -> fragment-tiled fp16 A tiles ----------------
// A tile layout: blocks (kt 0..15, mt 0..7) of 512B; block = 4x 8x8 matrices (ldmatrix.x4 A order).
__global__ void prep_feat(const float* __restrict__ f1, const float* __restrict__ f2) {
    int i = blockIdx.x, a = blockIdx.y, c = threadIdx.x;   // i < 8064 (pad -> 0)
    const float* f = a ? f2 : f1;
    float x = (i < NROWS) ? f[i * CDIM + c] : 0.f;
    __half hi = __float2half_rn(x);
    int tile = i >> 7, m = i & 127;
    int mt = m >> 4, mi8 = (m >> 3) & 1, mr = m & 7;
    int kt = c >> 4, kin = c & 15, kh = kin >> 3, kc = kin & 7;
    int q = kh * 2 + mi8;
    unsigned off = (unsigned)(((kt * 8 + mt) << 9) + (q << 7) + (mr << 4) + (kc << 1));
    *(__half*)(g_Asw[a] + (size_t)tile * ATILE_BYTES + off) = hi;
}

// ---------------- prep: gather memory rows -> fragment-tiled fp16 B stages + labels ----------------
// Stage (128-col chunk): blocks (kt 0..15, nt 0..7) of 512B (ldmatrix.x4 B order).
__global__ void prep_gather(const float* __restrict__ ul1, const float* __restrict__ ul2,
                            const int* __restrict__ sel1, const int* __restrict__ sel2,
                            const int* __restrict__ pl1, const int* __restrict__ pl2) {
    int j = blockIdx.x, c = threadIdx.x;   // j < 8064
    float x = 0.f;
    if (j < NROWS) {
        int n; const float* ul; const int* pl;
        if (j < 4000) { n = sel1[j];        ul = ul1; pl = pl1; }
        else          { n = sel2[j - 4000]; ul = ul2; pl = pl2; }
        int b = n / HW, hw = n - b * HW;
        x = ul[(b * CDIM + c) * HW + hw];
        if (c == 0) g_memlab[j] = (float)pl[n];
    }
    if (c == 1) {   // anchor labels (padded cols -> 0)
        g_alf[0][j] = (j < NROWS) ? (float)pl1[j] : 0.f;
        g_alf[1][j] = (j < NROWS) ? (float)pl2[j] : 0.f;
    }
    __half hi = __float2half_rn(x);
    int chunk = j >> 7, nn = j & 127;
    int kt = c >> 4, k16 = c & 15, kh = k16 >> 3, kc = k16 & 7;
    int nt = nn >> 4, ni8 = (nn >> 3) & 1, nr = nn & 7;
    int q = ni8 * 2 + kh;
    unsigned off = (unsigned)(((kt * 8 + nt) << 9) + (q << 7) + (nr << 4) + (kc << 1));
    *(__half*)(g_Bsw + (size_t)chunk * BSTAGE_BYTES + off) = hi;
}

// ---------------- prep: pos[i] = dot(feat1[i], feat2[i]) * 10 (exact fp32) ----------------
__global__ void prep_pos(const float* __restrict__ f1, const float* __restrict__ f2) {
    int warp = threadIdx.x >> 5, lane = threadIdx.x & 31;
    int i = blockIdx.x * 8 + warp;
    const float4* a = (const float4*)(f1 + i * CDIM);
    const float4* b = (const float4*)(f2 + i * CDIM);
    float s = 0.f;
    #pragma unroll
    for (int q = lane; q < CDIM / 4; q += 32) {
        float4 x = a[q], y = b[q];
        s += x.x * y.x + x.y * y.y + x.z * y.z + x.w * y.w;
    }
    #pragma unroll
    for (int off = 16; off > 0; off >>= 1) s += __shfl_xor_sync(0xffffffffu, s, off);
    if (lane == 0) g_pos[i] = s * 10.f;
}

// ---------------- main: single-pass fp16 mma.sync GEMM + fused masked softmax stats ----------------
// grid (63, 2), 288 threads: warps 0-7 = consumers (2M x 4N warps, warp tile 64x32),
// warp 8 = bulk-copy producer. 63 stages of 128 cols x full K.
__global__ __launch_bounds__(288, 1) void contrast_mm() {
    extern __shared__ char smem[];
    const unsigned sb = smem_u32(smem);
    const int tid = threadIdx.x, wid = tid >> 5, lane = tid & 31;
    const int mtile = blockIdx.x, anchor = blockIdx.y;

    if (tid == 0) {
        MBAR_INIT(sb + SM_AF, 1);
        MBAR_INIT(sb + SM_FULL + 0, 1);  MBAR_INIT(sb + SM_FULL + 16, 1);
        MBAR_INIT(sb + SM_FREE + 0, 8);  MBAR_INIT(sb + SM_FREE + 16, 8);
    }
    __syncthreads();

    if (wid < 8) {
        // -------- consumer --------
        const int wm = wid >> 2, wn = wid & 3;           // 2 M-warps x 4 N-warps
        const unsigned lanoff = (unsigned)(((lane >> 3) << 7) + ((lane & 7) << 4));
        const unsigned abase = sb + SM_A + lanoff;
        const float* __restrict__ labf = g_alf[anchor];

        float C[4][4][4];
        #pragma unroll
        for (int mi = 0; mi < 4; mi++)
            #pragma unroll
            for (int nj = 0; nj < 4; nj++)
                #pragma unroll
                for (int e = 0; e < 4; e++) C[mi][nj][e] = 0.f;
        float rmx[4][2], tal[4][2], t1a[4][2];
        #pragma unroll
        for (int mi = 0; mi < 4; mi++)
            #pragma unroll
            for (int rh = 0; rh < 2; rh++) { rmx[mi][rh] = -1e30f; tal[mi][rh] = 0.f; t1a[mi][rh] = 0.f; }

        MBAR_WAIT(sb + SM_AF, 0);   // A tile resident

        for (int s = 0; s < NSTAGE; s++) {
            const int buf = s & 1;
            MBAR_WAIT(sb + SM_FULL + 16 * buf, (s >> 1) & 1);
            const unsigned bbase = sb + SM_B + (buf << 16) + lanoff;
            #pragma unroll
            for (int kt = 0; kt < 16; kt++) {
                unsigned Ah[4][4], Bf[2][4];
                #pragma unroll
                for (int mi = 0; mi < 4; mi++)
                    LDSM4(Ah[mi], abase + (unsigned)((kt * 8 + wm * 4 + mi) << 9));
                #pragma unroll
                for (int bj = 0; bj < 2; bj++)
                    LDSM4(Bf[bj], bbase + (unsigned)((kt * 8 + wn * 2 + bj) << 9));
                #pragma unroll
                for (int mi = 0; mi < 4; mi++)
                    #pragma unroll
                    for (int nj = 0; nj < 4; nj++) {
                        const int bj = nj >> 1, s2 = (nj & 1) * 2;
                        MMA_FP16(C[mi][nj], Ah[mi], Bf[bj][s2], Bf[bj][s2 + 1]);
                    }
            }
            if (lane == 0) MBAR_ARRIVE(sb + SM_FREE + 16 * buf);

            // fold this 128-col chunk into per-row stats, reset C
            const int cb = s * 128 + wn * 32 + ((lane & 3) << 1);
            float l0[4], l1[4];
            #pragma unroll
            for (int nj = 0; nj < 4; nj++) {
                l0[nj] = labf[cb + nj * 8];
                l1[nj] = labf[cb + nj * 8 + 1];
            }
            #pragma unroll
            for (int mi = 0; mi < 4; mi++)
                #pragma unroll
                for (int nj = 0; nj < 4; nj++)
                    #pragma unroll
                    for (int e = 0; e < 4; e++) {
                        const int rh = e >> 1;
                        float sv = C[mi][nj][e];
                        rmx[mi][rh] = fmaxf(rmx[mi][rh], sv);
                        float ex = __expf(fmaf(sv, 10.f, -12.f));
                        tal[mi][rh] += ex;
                        t1a[mi][rh] = fmaf(ex, (e & 1) ? l1[nj] : l0[nj], t1a[mi][rh]);
                        C[mi][nj][e] = 0.f;
                    }
        }

        // quad reduce (lanes sharing a row differ in lane&3)
        #pragma unroll
        for (int mi = 0; mi < 4; mi++)
            #pragma unroll
            for (int rh = 0; rh < 2; rh++) {
                #pragma unroll
                for (int off = 1; off <= 2; off <<= 1) {
                    rmx[mi][rh] = fmaxf(rmx[mi][rh], __shfl_xor_sync(0xffffffffu, rmx[mi][rh], off));
                    tal[mi][rh] += __shfl_xor_sync(0xffffffffu, tal[mi][rh], off);
                    t1a[mi][rh] += __shfl_xor_sync(0xffffffffu, t1a[mi][rh], off);
                }
            }
        __syncthreads();   // all warps done reading smem before stats overwrite it
        if ((lane & 3) == 0) {
            float* sred = (float*)(smem + SM_A);
            #pragma unroll
            for (int mi = 0; mi < 4; mi++)
                #pragma unroll
                for (int rh = 0; rh < 2; rh++) {
                    int r = wm * 64 + mi * 16 + rh * 8 + (lane >> 2);
                    float* p = sred + (wn * 128 + r) * 4;
                    p[0] = rmx[mi][rh]; p[1] = tal[mi][rh]; p[2] = t1a[mi][rh];
                }
        }
    } else {
        // -------- producer --------
        if (elect_one_pred()) {
            MBAR_EXPECT_TX(sb + SM_AF, ATILE_BYTES);
            BULK_G2S(sb + SM_A, g_Asw[anchor] + (size_t)mtile * ATILE_BYTES,
                     (unsigned)ATILE_BYTES, sb + SM_AF);
            for (int s = 0; s < NSTAGE; s++) {
                const int buf = s & 1;
                if (s >= 2) MBAR_WAIT(sb + SM_FREE + 16 * buf, ((s - 2) >> 1) & 1);
                MBAR_EXPECT_TX(sb + SM_FULL + 16 * buf, BSTAGE_BYTES);
                BULK_G2S(sb + SM_B + (buf << 16), g_Bsw + (size_t)s * BSTAGE_BYTES,
                         (unsigned)BSTAGE_BYTES, sb + SM_FULL + 16 * buf);
            }
        }
        __syncthreads();   // matches consumers' pre-stats barrier
    }

    __syncthreads();
    if (tid < MT) {
        const float* sred = (const float*)(smem + SM_A);
        float rmax = -1e30f, tall = 0.f, t1v = 0.f;
        #pragma unroll
        for (int w = 0; w < 4; w++) {
            const float* p = sred + (w * 128 + tid) * 4;
            rmax = fmaxf(rmax, p[0]);
            tall += p[1];
            t1v  += p[2];
        }
        tall -= 64.f * __expf(-12.f);   // remove padded-column contributions (exact cancel)
        const int i = mtile * MT + tid;
        if (i < NROWS) {
            float posv = g_pos[i];
            float mfull = fmaxf(rmax * 10.f, posv);
            float tsel = (g_memlab[i] == 0.f) ? t1v : (tall - t1v);
            float epos = __expf(posv - mfull);
            float sum = epos + tsel * __expf(12.f - mfull);
            g_L[anchor][i] = -logf(epos / (sum + 1e-8f) + 1e-8f);
        }
    }
}

// ---------------- deterministic final reduction ----------------
__global__ void finalize(const float* __restrict__ plog1, const float* __restrict__ plog2,
                         float* __restrict__ out) {
    __shared__ float sm[256][4];
    int tid = threadIdx.x;
    float n1 = 0.f, c1 = 0.f, n2 = 0.f, c2 = 0.f;
    for (int i = tid; i < NROWS; i += 256) {
        float q1 = plog1[i], q2 = plog2[i];
        if (q2 > 0.7f && q1 < q2) { n1 += g_L[0][i]; c1 += 1.f; }
        if (q1 > 0.7f && q2 < q1) { n2 += g_L[1][i]; c2 += 1.f; }
    }
    sm[tid][0] = n1; sm[tid][1] = c1; sm[tid][2] = n2; sm[tid][3] = c2;
    __syncthreads();
    for (int s = 128; s > 0; s >>= 1) {
        if (tid < s) {
            #pragma unroll
            for (int q = 0; q < 4; q++) sm[tid][q] += sm[tid + s][q];
        }
        __syncthreads();
    }
    if (tid == 0)
        out[0] = sm[0][0] / (sm[0][1] + 1e-12f) + sm[0][2] / (sm[0][3] + 1e-12f);
}

// ---------------- launch ----------------
extern "C" void kernel_launch(void* const* d_in, const int* in_sizes, int n_in,
                              void* d_out, int out_size) {
    const float* feat1 = (const float*)d_in[0];
    const float* feat2 = (const float*)d_in[1];
    const float* ul1   = (const float*)d_in[2];
    const float* ul2   = (const float*)d_in[3];
    const int*   pl1   = (const int*)d_in[4];
    const int*   pl2   = (const int*)d_in[5];
    const float* plog1 = (const float*)d_in[6];
    const float* plog2 = (const float*)d_in[7];
    const int*   sel1  = (const int*)d_in[8];
    const int*   sel2  = (const int*)d_in[9];
    float* out = (float*)d_out;

    cudaFuncSetAttribute(contrast_mm, cudaFuncAttributeMaxDynamicSharedMemorySize, SMEM_TOTAL);

    prep_feat<<<dim3(NPAD, 2), 256>>>(feat1, feat2);
    prep_gather<<<NPAD, 256>>>(ul1, ul2, sel1, sel2, pl1, pl2);
    prep_pos<<<NROWS / 8, 256>>>(feat1, feat2);
    contrast_mm<<<dim3(MTILES, 2), 288, SMEM_TOTAL>>>();
    finalize<<<1, 256>>>(plog1, plog2, out);
}

// round 5
// speedup vs baseline: 10.1901x; 1.0496x over previous
#include <cuda_runtime.h>
#include <cuda_fp16.h>

#define NROWS 8000
#define NPAD  8064
#define CDIM  256
#define HW    1600
#define MT    128
#define MTILES 63
#define NSTAGE 63
#define ATILE_BYTES  65536    // 128 rows x 256 k x 2B fp16, fragment-tiled
#define BSTAGE_BYTES 65536    // 128 cols x 256 k x 2B fp16, fragment-tiled

#define K_EX2A 14.4269504089f    // 10*log2(e)
#define K_EX2B -17.3123404907f   // -12*log2(e)

// ---- dynamic smem map ----
#define SM_AF   0             // A-full barrier
#define SM_FULL 16            // full[s] at +16*s
#define SM_FREE 48            // free[s] at +16*s
#define SM_A    1024          // 65536
#define SM_B    66560         // 2 x 65536
#define SMEM_TOTAL 197632

// ---------------- device scratch ----------------
__device__ __align__(1024) unsigned char g_Asw[2][(size_t)MTILES * ATILE_BYTES];
__device__ __align__(1024) unsigned char g_Bsw[(size_t)NSTAGE * BSTAGE_BYTES];
__device__ float g_memlab[NROWS];
__device__ float g_pos[NROWS];
__device__ float g_alf[2][NPAD];
__device__ float g_L[2][NROWS];

// ---------------- PTX helpers ----------------
__device__ __forceinline__ unsigned elect_one_pred() {
    unsigned pred;
    asm volatile("{\n\t.reg .pred p;\n\telect.sync _|p, 0xFFFFFFFF;\n\tselp.b32 %0, 1, 0, p;\n\t}"
                 : "=r"(pred));
    return pred;
}
__device__ __forceinline__ unsigned smem_u32(const void* p) {
    unsigned a;
    asm("{ .reg .u64 t; cvta.to.shared.u64 t, %1; cvt.u32.u64 %0, t; }" : "=r"(a) : "l"(p));
    return a;
}
__device__ __forceinline__ float ex2f(float x) {
    float r;
    asm("ex2.approx.ftz.f32 %0, %1;" : "=f"(r) : "f"(x));
    return r;
}
#define MBAR_INIT(addr, cnt) \
    asm volatile("mbarrier.init.shared.b64 [%0], %1;" :: "r"(addr), "r"(cnt) : "memory")
#define MBAR_EXPECT_TX(addr, bytes) \
    asm volatile("mbarrier.arrive.expect_tx.shared.b64 _, [%0], %1;" :: "r"(addr), "r"(bytes) : "memory")
#define MBAR_ARRIVE(addr) \
    asm volatile("mbarrier.arrive.shared.b64 _, [%0];" :: "r"(addr) : "memory")
#define MBAR_WAIT(addr, ph) do { \
    unsigned _m = (addr), _p = (ph), _d; \
    asm volatile("{\n\t.reg .pred p;\n\tmbarrier.try_wait.parity.acquire.cta.shared::cta.b64 p, [%1], %2;\n\tselp.b32 %0, 1, 0, p;\n\t}" \
                 : "=r"(_d) : "r"(_m), "r"(_p) : "memory"); \
    if (!_d) { \
        asm volatile("{\n\t.reg .pred P1;\n\tWL%=:\n\tmbarrier.try_wait.parity.acquire.cta.shared::cta.b64 P1, [%0], %1, 0x989680;\n\t@P1 bra.uni WD%=;\n\tbra.uni WL%=;\n\tWD%=:\n\t}" \
                     :: "r"(_m), "r"(_p) : "memory"); \
    } } while (0)
#define BULK_G2S(dst, src, bytes, mbar) \
    asm volatile("cp.async.bulk.shared::cluster.global.mbarrier::complete_tx::bytes [%0], [%1], %2, [%3];" \
                 :: "r"(dst), "l"(src), "r"(bytes), "r"(mbar) : "memory")
#define LDSM4(r, addr) \
    asm volatile("ldmatrix.sync.aligned.m8n8.x4.shared.b16 {%0,%1,%2,%3}, [%4];" \
                 : "=r"((r)[0]), "=r"((r)[1]), "=r"((r)[2]), "=r"((r)[3]) : "r"(addr))
#define MMA_FP16(c, a, b0, b1) \
    asm volatile("mma.sync.aligned.m16n8k16.row.col.f32.f16.f16.f32 " \
                 "{%0,%1,%2,%3}, {%4,%5,%6,%7}, {%8,%9}, {%0,%1,%2,%3};" \
                 : "+f"((c)[0]), "+f"((c)[1]), "+f"((c)[2]), "+f"((c)[3]) \
                 : "r"((a)[0]), "r"((a)[1]), "r"((a)[2]), "r"((a)[3]), "r"(b0), "r"(b1))

// ---------------- prep: feats -> both fp16 A tiles + pos dot (merged) ----------------
// A tile layout: blocks (kt 0..15, mt 0..7) of 512B; block = 4x 8x8 matrices (ldmatrix.x4 A order).
__global__ void prep_fp(const float* __restrict__ f1, const float* __restrict__ f2) {
    int i = blockIdx.x, c = threadIdx.x;   // i < 8064 (pad -> 0)
    float x1 = 0.f, x2 = 0.f;
    if (i < NROWS) { x1 = f1[i * CDIM + c]; x2 = f2[i * CDIM + c]; }
    int tile = i >> 7, m = i & 127;
    int mt = m >> 4, mi8 = (m >> 3) & 1, mr = m & 7;
    int kt = c >> 4, kin = c & 15, kh = kin >> 3, kc = kin & 7;
    int q = kh * 2 + mi8;
    unsigned off = (unsigned)(((kt * 8 + mt) << 9) + (q << 7) + (mr << 4) + (kc << 1));
    *(__half*)(g_Asw[0] + (size_t)tile * ATILE_BYTES + off) = __float2half_rn(x1);
    *(__half*)(g_Asw[1] + (size_t)tile * ATILE_BYTES + off) = __float2half_rn(x2);
    // pos dot (exact fp32)
    float p = x1 * x2;
    #pragma unroll
    for (int o = 16; o > 0; o >>= 1) p += __shfl_xor_sync(0xffffffffu, p, o);
    __shared__ float ws[8];
    if ((c & 31) == 0) ws[c >> 5] = p;
    __syncthreads();
    if (c == 0 && i < NROWS) {
        float s = ws[0] + ws[1] + ws[2] + ws[3] + ws[4] + ws[5] + ws[6] + ws[7];
        g_pos[i] = s * 10.f;
    }
}

// ---------------- prep: gather memory rows -> fragment-tiled fp16 B stages + labels ----------------
__global__ void prep_gather(const float* __restrict__ ul1, const float* __restrict__ ul2,
                            const int* __restrict__ sel1, const int* __restrict__ sel2,
                            const int* __restrict__ pl1, const int* __restrict__ pl2) {
    int j = blockIdx.x, c = threadIdx.x;   // j < 8064
    float x = 0.f;
    if (j < NROWS) {
        int n; const float* ul; const int* pl;
        if (j < 4000) { n = sel1[j];        ul = ul1; pl = pl1; }
        else          { n = sel2[j - 4000]; ul = ul2; pl = pl2; }
        int b = n / HW, hw = n - b * HW;
        x = ul[(b * CDIM + c) * HW + hw];
        if (c == 0) g_memlab[j] = (float)pl[n];
    }
    if (c == 1) {   // anchor labels (padded cols -> 0)
        g_alf[0][j] = (j < NROWS) ? (float)pl1[j] : 0.f;
        g_alf[1][j] = (j < NROWS) ? (float)pl2[j] : 0.f;
    }
    __half hi = __float2half_rn(x);
    int chunk = j >> 7, nn = j & 127;
    int kt = c >> 4, k16 = c & 15, kh = k16 >> 3, kc = k16 & 7;
    int nt = nn >> 4, ni8 = (nn >> 3) & 1, nr = nn & 7;
    int q = ni8 * 2 + kh;
    unsigned off = (unsigned)(((kt * 8 + nt) << 9) + (q << 7) + (nr << 4) + (kc << 1));
    *(__half*)(g_Bsw + (size_t)chunk * BSTAGE_BYTES + off) = hi;
}

// ---------------- main: fp16 mma.sync GEMM with fold interleaved into MMA stream ----------------
// grid (63, 2), 288 threads: warps 0-7 = consumers (2M x 4N warps, warp tile 64x32),
// warp 8 = bulk-copy producer. 63 stages of 128 cols x full K.
__global__ __launch_bounds__(288, 1) void contrast_mm() {
    extern __shared__ char smem[];
    const unsigned sb = smem_u32(smem);
    const int tid = threadIdx.x, wid = tid >> 5, lane = tid & 31;
    const int mtile = blockIdx.x, anchor = blockIdx.y;

    if (tid == 0) {
        MBAR_INIT(sb + SM_AF, 1);
        MBAR_INIT(sb + SM_FULL + 0, 1);  MBAR_INIT(sb + SM_FULL + 16, 1);
        MBAR_INIT(sb + SM_FREE + 0, 8);  MBAR_INIT(sb + SM_FREE + 16, 8);
    }
    __syncthreads();

    if (wid < 8) {
        // -------- consumer --------
        const int wm = wid >> 2, wn = wid & 3;           // 2 M-warps x 4 N-warps
        const unsigned lanoff = (unsigned)(((lane >> 3) << 7) + ((lane & 7) << 4));
        const unsigned abase = sb + SM_A + lanoff;
        const float* __restrict__ labf = g_alf[anchor];

        float C[4][4][4];
        #pragma unroll
        for (int mi = 0; mi < 4; mi++)
            #pragma unroll
            for (int nj = 0; nj < 4; nj++)
                #pragma unroll
                for (int e = 0; e < 4; e++) C[mi][nj][e] = 0.f;
        float rmx[4][2], tal[4][2], t1a[4][2];
        #pragma unroll
        for (int mi = 0; mi < 4; mi++)
            #pragma unroll
            for (int rh = 0; rh < 2; rh++) { rmx[mi][rh] = -1e30f; tal[mi][rh] = 0.f; t1a[mi][rh] = 0.f; }

        MBAR_WAIT(sb + SM_AF, 0);   // A tile resident

        for (int s = 0; s < NSTAGE; s++) {
            const int buf = s & 1;
            MBAR_WAIT(sb + SM_FULL + 16 * buf, (s >> 1) & 1);
            const unsigned bbase = sb + SM_B + (buf << 16) + lanoff;

            // stage labels (L1-resident after stage 0 of the first CTA wave)
            const int cb = s * 128 + wn * 32 + ((lane & 3) << 1);
            float l0[4], l1[4];
            #pragma unroll
            for (int nj = 0; nj < 4; nj++) {
                l0[nj] = labf[cb + nj * 8];
                l1[nj] = labf[cb + nj * 8 + 1];
            }

            #pragma unroll
            for (int kb = 0; kb < 2; kb++) {
                #pragma unroll
                for (int mi = 0; mi < 4; mi++) {
                    unsigned Ar[8][4];
                    #pragma unroll
                    for (int g = 0; g < 8; g++)
                        LDSM4(Ar[g], abase + (unsigned)((((kb * 8 + g) * 8) + wm * 4 + mi) << 9));
                    #pragma unroll
                    for (int bj = 0; bj < 2; bj++) {
                        #pragma unroll
                        for (int g = 0; g < 8; g++) {
                            unsigned Bf[4];
                            LDSM4(Bf, bbase + (unsigned)((((kb * 8 + g) * 8) + wn * 2 + bj) << 9));
                            MMA_FP16(C[mi][bj * 2 + 0], Ar[g], Bf[0], Bf[1]);
                            MMA_FP16(C[mi][bj * 2 + 1], Ar[g], Bf[2], Bf[3]);
                        }
                    }
                    if (kb == 1) {
                        // fold this m16 tile now — interleaves with next tile's MMAs
                        #pragma unroll
                        for (int nj = 0; nj < 4; nj++)
                            #pragma unroll
                            for (int e = 0; e < 4; e++) {
                                const int rh = e >> 1;
                                float sv = C[mi][nj][e];
                                rmx[mi][rh] = fmaxf(rmx[mi][rh], sv);
                                float ex = ex2f(fmaf(sv, K_EX2A, K_EX2B));  // = e^(10*sv-12)
                                tal[mi][rh] += ex;
                                t1a[mi][rh] = fmaf(ex, (e & 1) ? l1[nj] : l0[nj], t1a[mi][rh]);
                                C[mi][nj][e] = 0.f;
                            }
                    }
                }
            }
            if (lane == 0) MBAR_ARRIVE(sb + SM_FREE + 16 * buf);
        }

        // quad reduce (lanes sharing a row differ in lane&3)
        #pragma unroll
        for (int mi = 0; mi < 4; mi++)
            #pragma unroll
            for (int rh = 0; rh < 2; rh++) {
                #pragma unroll
                for (int off = 1; off <= 2; off <<= 1) {
                    rmx[mi][rh] = fmaxf(rmx[mi][rh], __shfl_xor_sync(0xffffffffu, rmx[mi][rh], off));
                    tal[mi][rh] += __shfl_xor_sync(0xffffffffu, tal[mi][rh], off);
                    t1a[mi][rh] += __shfl_xor_sync(0xffffffffu, t1a[mi][rh], off);
                }
            }
        __syncthreads();   // all warps done reading smem before stats overwrite it
        if ((lane & 3) == 0) {
            float* sred = (float*)(smem + SM_A);
            #pragma unroll
            for (int mi = 0; mi < 4; mi++)
                #pragma unroll
                for (int rh = 0; rh < 2; rh++) {
                    int r = wm * 64 + mi * 16 + rh * 8 + (lane >> 2);
                    float* p = sred + (wn * 128 + r) * 4;
                    p[0] = rmx[mi][rh]; p[1] = tal[mi][rh]; p[2] = t1a[mi][rh];
                }
        }
    } else {
        // -------- producer --------
        if (elect_one_pred()) {
            MBAR_EXPECT_TX(sb + SM_AF, ATILE_BYTES);
            BULK_G2S(sb + SM_A, g_Asw[anchor] + (size_t)mtile * ATILE_BYTES,
                     (unsigned)ATILE_BYTES, sb + SM_AF);
            for (int s = 0; s < NSTAGE; s++) {
                const int buf = s & 1;
                if (s >= 2) MBAR_WAIT(sb + SM_FREE + 16 * buf, ((s - 2) >> 1) & 1);
                MBAR_EXPECT_TX(sb + SM_FULL + 16 * buf, BSTAGE_BYTES);
                BULK_G2S(sb + SM_B + (buf << 16), g_Bsw + (size_t)s * BSTAGE_BYTES,
                         (unsigned)BSTAGE_BYTES, sb + SM_FULL + 16 * buf);
            }
        }
        __syncthreads();   // matches consumers' pre-stats barrier
    }

    __syncthreads();
    if (tid < MT) {
        const float* sred = (const float*)(smem + SM_A);
        float rmax = -1e30f, tall = 0.f, t1v = 0.f;
        #pragma unroll
        for (int w = 0; w < 4; w++) {
            const float* p = sred + (w * 128 + tid) * 4;
            rmax = fmaxf(rmax, p[0]);
            tall += p[1];
            t1v  += p[2];
        }
        tall -= 64.f * ex2f(K_EX2B);   // remove padded-column contributions (bitwise cancel)
        const int i = mtile * MT + tid;
        if (i < NROWS) {
            float posv = g_pos[i];
            float mfull = fmaxf(rmax * 10.f, posv);
            float tsel = (g_memlab[i] == 0.f) ? t1v : (tall - t1v);
            float epos = __expf(posv - mfull);
            float sum = epos + tsel * __expf(12.f - mfull);
            g_L[anchor][i] = -logf(epos / (sum + 1e-8f) + 1e-8f);
        }
    }
}

// ---------------- deterministic final reduction ----------------
__global__ void finalize(const float* __restrict__ plog1, const float* __restrict__ plog2,
                         float* __restrict__ out) {
    __shared__ float sm[256][4];
    int tid = threadIdx.x;
    float n1 = 0.f, c1 = 0.f, n2 = 0.f, c2 = 0.f;
    for (int i = tid; i < NROWS; i += 256) {
        float q1 = plog1[i], q2 = plog2[i];
        if (q2 > 0.7f && q1 < q2) { n1 += g_L[0][i]; c1 += 1.f; }
        if (q1 > 0.7f && q2 < q1) { n2 += g_L[1][i]; c2 += 1.f; }
    }
    sm[tid][0] = n1; sm[tid][1] = c1; sm[tid][2] = n2; sm[tid][3] = c2;
    __syncthreads();
    for (int s = 128; s > 0; s >>= 1) {
        if (tid < s) {
            #pragma unroll
            for (int q = 0; q < 4; q++) sm[tid][q] += sm[tid + s][q];
        }
        __syncthreads();
    }
    if (tid == 0)
        out[0] = sm[0][0] / (sm[0][1] + 1e-12f) + sm[0][2] / (sm[0][3] + 1e-12f);
}

// ---------------- launch ----------------
extern "C" void kernel_launch(void* const* d_in, const int* in_sizes, int n_in,
                              void* d_out, int out_size) {
    const float* feat1 = (const float*)d_in[0];
    const float* feat2 = (const float*)d_in[1];
    const float* ul1   = (const float*)d_in[2];
    const float* ul2   = (const float*)d_in[3];
    const int*   pl1   = (const int*)d_in[4];
    const int*   pl2   = (const int*)d_in[5];
    const float* plog1 = (const float*)d_in[6];
    const float* plog2 = (const float*)d_in[7];
    const int*   sel1  = (const int*)d_in[8];
    const int*   sel2  = (const int*)d_in[9];
    float* out = (float*)d_out;

    cudaFuncSetAttribute(contrast_mm, cudaFuncAttributeMaxDynamicSharedMemorySize, SMEM_TOTAL);

    prep_fp<<<NPAD, 256>>>(feat1, feat2);
    prep_gather<<<NPAD, 256>>>(ul1, ul2, sel1, sel2, pl1, pl2);
    contrast_mm<<<dim3(MTILES, 2), 288, SMEM_TOTAL>>>();
    finalize<<<1, 256>>>(plog1, plog2, out);
}

// round 6
// speedup vs baseline: 10.7868x; 1.0586x over previous
#include <cuda_runtime.h>
#include <cuda_fp16.h>

#define NROWS 8000
#define NPAD  8064
#define CDIM  256
#define HW    1600
#define MT    128
#define MTILES 63
#define NSTAGE 63
#define ATILE_BYTES  65536    // 128 rows x 256 k x 2B fp16, fragment-tiled
#define BSTAGE_BYTES 65536    // 128 cols x 256 k x 2B fp16, fragment-tiled

#define K_EX2A 14.4269504089f    // 10*log2(e)
#define K_EX2B -17.3123404907f   // -12*log2(e)

// ---- dynamic smem map ----
#define SM_AF   0             // A-full barrier
#define SM_FULL 16            // full[s] at +16*s
#define SM_FREE 48            // free[s] at +16*s
#define SM_A    1024          // 65536
#define SM_B    66560         // 2 x 65536
#define SMEM_TOTAL 197632

// ---------------- device scratch ----------------
__device__ __align__(1024) unsigned char g_Asw[2][(size_t)MTILES * ATILE_BYTES];
__device__ __align__(1024) unsigned char g_Bsw[(size_t)NSTAGE * BSTAGE_BYTES];
__device__ float g_memlab[NROWS];
__device__ float g_pos[NROWS];
__device__ float g_alf[2][NPAD];
__device__ float2 g_part[2][MTILES];   // per-(anchor, mtile) masked (sum, count)

// ---------------- PTX helpers ----------------
__device__ __forceinline__ unsigned elect_one_pred() {
    unsigned pred;
    asm volatile("{\n\t.reg .pred p;\n\telect.sync _|p, 0xFFFFFFFF;\n\tselp.b32 %0, 1, 0, p;\n\t}"
                 : "=r"(pred));
    return pred;
}
__device__ __forceinline__ unsigned smem_u32(const void* p) {
    unsigned a;
    asm("{ .reg .u64 t; cvta.to.shared.u64 t, %1; cvt.u32.u64 %0, t; }" : "=r"(a) : "l"(p));
    return a;
}
__device__ __forceinline__ float ex2f(float x) {
    float r;
    asm("ex2.approx.ftz.f32 %0, %1;" : "=f"(r) : "f"(x));
    return r;
}
#define MBAR_INIT(addr, cnt) \
    asm volatile("mbarrier.init.shared.b64 [%0], %1;" :: "r"(addr), "r"(cnt) : "memory")
#define MBAR_EXPECT_TX(addr, bytes) \
    asm volatile("mbarrier.arrive.expect_tx.shared.b64 _, [%0], %1;" :: "r"(addr), "r"(bytes) : "memory")
#define MBAR_ARRIVE(addr) \
    asm volatile("mbarrier.arrive.shared.b64 _, [%0];" :: "r"(addr) : "memory")
#define MBAR_WAIT(addr, ph) do { \
    unsigned _m = (addr), _p = (ph), _d; \
    asm volatile("{\n\t.reg .pred p;\n\tmbarrier.try_wait.parity.acquire.cta.shared::cta.b64 p, [%1], %2;\n\tselp.b32 %0, 1, 0, p;\n\t}" \
                 : "=r"(_d) : "r"(_m), "r"(_p) : "memory"); \
    if (!_d) { \
        asm volatile("{\n\t.reg .pred P1;\n\tWL%=:\n\tmbarrier.try_wait.parity.acquire.cta.shared::cta.b64 P1, [%0], %1, 0x989680;\n\t@P1 bra.uni WD%=;\n\tbra.uni WL%=;\n\tWD%=:\n\t}" \
                     :: "r"(_m), "r"(_p) : "memory"); \
    } } while (0)
#define BULK_G2S(dst, src, bytes, mbar) \
    asm volatile("cp.async.bulk.shared::cluster.global.mbarrier::complete_tx::bytes [%0], [%1], %2, [%3];" \
                 :: "r"(dst), "l"(src), "r"(bytes), "r"(mbar) : "memory")
#define LDSM4(r, addr) \
    asm volatile("ldmatrix.sync.aligned.m8n8.x4.shared.b16 {%0,%1,%2,%3}, [%4];" \
                 : "=r"((r)[0]), "=r"((r)[1]), "=r"((r)[2]), "=r"((r)[3]) : "r"(addr))
#define MMA_FP16(c, a, b0, b1) \
    asm volatile("mma.sync.aligned.m16n8k16.row.col.f32.f16.f16.f32 " \
                 "{%0,%1,%2,%3}, {%4,%5,%6,%7}, {%8,%9}, {%0,%1,%2,%3};" \
                 : "+f"((c)[0]), "+f"((c)[1]), "+f"((c)[2]), "+f"((c)[3]) \
                 : "r"((a)[0]), "r"((a)[1]), "r"((a)[2]), "r"((a)[3]), "r"(b0), "r"(b1))

__device__ __forceinline__ unsigned pack2(float a, float b) {
    __half2 h = __floats2half2_rn(a, b);   // a -> low half (lower address)
    return *(unsigned*)&h;
}

// ---------------- merged prep ----------------
// blocks [0, 2016): feats -> both A tiles (8B stores) + pos dot
// blocks [2016, 4032): gather memory rows -> B stages (8B stores) + labels
__global__ void prep_all(const float* __restrict__ f1, const float* __restrict__ f2,
                         const float* __restrict__ ul1, const float* __restrict__ ul2,
                         const int* __restrict__ sel1, const int* __restrict__ sel2,
                         const int* __restrict__ pl1, const int* __restrict__ pl2) {
    __shared__ float ws[8];
    const int t = threadIdx.x;
    const int r = t >> 6, sub = t & 63;
    const int kc2 = sub & 1, kh = (sub >> 1) & 1, kt = sub >> 2;
    const int k0 = kt * 16 + kh * 8 + kc2 * 4;

    if (blockIdx.x < 2016) {
        // ---- feats ----
        const int i = blockIdx.x * 4 + r;
        float4 x1 = make_float4(0.f, 0.f, 0.f, 0.f), x2 = x1;
        if (i < NROWS) {
            x1 = *(const float4*)(f1 + i * CDIM + k0);
            x2 = *(const float4*)(f2 + i * CDIM + k0);
        }
        const int tile = i >> 7, m = i & 127;
        const int mt = m >> 4, mi8 = (m >> 3) & 1, mr = m & 7;
        const int q = kh * 2 + mi8;
        const unsigned off = (unsigned)(((kt * 8 + mt) << 9) + (q << 7) + (mr << 4) + kc2 * 8);
        uint2 u1 = make_uint2(pack2(x1.x, x1.y), pack2(x1.z, x1.w));
        uint2 u2 = make_uint2(pack2(x2.x, x2.y), pack2(x2.z, x2.w));
        *(uint2*)(g_Asw[0] + (size_t)tile * ATILE_BYTES + off) = u1;
        *(uint2*)(g_Asw[1] + (size_t)tile * ATILE_BYTES + off) = u2;
        // pos dot (exact fp32)
        float p = x1.x * x2.x + x1.y * x2.y + x1.z * x2.z + x1.w * x2.w;
        #pragma unroll
        for (int o = 16; o > 0; o >>= 1) p += __shfl_xor_sync(0xffffffffu, p, o);
        if ((t & 31) == 0) ws[t >> 5] = p;
        __syncthreads();
        if (sub == 0 && i < NROWS)
            g_pos[i] = (ws[r * 2] + ws[r * 2 + 1]) * 10.f;
    } else {
        // ---- gather ----
        const int j = (blockIdx.x - 2016) * 4 + r;
        float x0 = 0.f, xa = 0.f, xb = 0.f, xc = 0.f;
        if (j < NROWS) {
            int n; const float* ul; const int* pl;
            if (j < 4000) { n = sel1[j];        ul = ul1; pl = pl1; }
            else          { n = sel2[j - 4000]; ul = ul2; pl = pl2; }
            const int b = n / HW, hw = n - b * HW;
            const float* src = ul + (size_t)(b * CDIM + k0) * HW + hw;
            x0 = src[0]; xa = src[HW]; xb = src[2 * HW]; xc = src[3 * HW];
            if (sub == 0) g_memlab[j] = (float)pl[n];
        }
        if (sub == 1) {   // anchor labels (padded -> 0)
            g_alf[0][j] = (j < NROWS) ? (float)pl1[j] : 0.f;
            g_alf[1][j] = (j < NROWS) ? (float)pl2[j] : 0.f;
        }
        const int chunk = j >> 7, nn = j & 127;
        const int nt = nn >> 4, ni8 = (nn >> 3) & 1, nr = nn & 7;
        const int q = ni8 * 2 + kh;
        const unsigned off = (unsigned)(((kt * 8 + nt) << 9) + (q << 7) + (nr << 4) + kc2 * 8);
        *(uint2*)(g_Bsw + (size_t)chunk * BSTAGE_BYTES + off) =
            make_uint2(pack2(x0, xa), pack2(xb, xc));
    }
}

// ---------------- main: fp16 mma.sync GEMM + fused stats + in-kernel loss partials ----------------
// grid (63, 2), 288 threads: warps 0-7 = consumers (2M x 4N), warp 8 = producer.
__global__ __launch_bounds__(288, 1) void contrast_mm(const float* __restrict__ plog1,
                                                      const float* __restrict__ plog2) {
    extern __shared__ char smem[];
    __shared__ float red2[9][2];
    const unsigned sb = smem_u32(smem);
    const int tid = threadIdx.x, wid = tid >> 5, lane = tid & 31;
    const int mtile = blockIdx.x, anchor = blockIdx.y;

    if (tid == 0) {
        MBAR_INIT(sb + SM_AF, 1);
        MBAR_INIT(sb + SM_FULL + 0, 1);  MBAR_INIT(sb + SM_FULL + 16, 1);
        MBAR_INIT(sb + SM_FREE + 0, 8);  MBAR_INIT(sb + SM_FREE + 16, 8);
    }
    __syncthreads();

    if (wid < 8) {
        // -------- consumer --------
        const int wm = wid >> 2, wn = wid & 3;           // 2 M-warps x 4 N-warps
        const unsigned lanoff = (unsigned)(((lane >> 3) << 7) + ((lane & 7) << 4));
        const unsigned abase = sb + SM_A + lanoff;
        const float* __restrict__ labf = g_alf[anchor];

        float C[4][4][4];
        #pragma unroll
        for (int mi = 0; mi < 4; mi++)
            #pragma unroll
            for (int nj = 0; nj < 4; nj++)
                #pragma unroll
                for (int e = 0; e < 4; e++) C[mi][nj][e] = 0.f;
        float rmx[4][2], tal[4][2], t1a[4][2];
        #pragma unroll
        for (int mi = 0; mi < 4; mi++)
            #pragma unroll
            for (int rh = 0; rh < 2; rh++) { rmx[mi][rh] = -1e30f; tal[mi][rh] = 0.f; t1a[mi][rh] = 0.f; }

        MBAR_WAIT(sb + SM_AF, 0);   // A tile resident

        for (int s = 0; s < NSTAGE; s++) {
            const int buf = s & 1;
            MBAR_WAIT(sb + SM_FULL + 16 * buf, (s >> 1) & 1);
            const unsigned bbase = sb + SM_B + (buf << 16) + lanoff;

            const int cb = s * 128 + wn * 32 + ((lane & 3) << 1);
            float l0[4], l1[4];
            #pragma unroll
            for (int nj = 0; nj < 4; nj++) {
                l0[nj] = labf[cb + nj * 8];
                l1[nj] = labf[cb + nj * 8 + 1];
            }

            #pragma unroll
            for (int kb = 0; kb < 2; kb++) {
                #pragma unroll
                for (int mi = 0; mi < 4; mi++) {
                    unsigned Ar[8][4];
                    #pragma unroll
                    for (int g = 0; g < 8; g++)
                        LDSM4(Ar[g], abase + (unsigned)((((kb * 8 + g) * 8) + wm * 4 + mi) << 9));
                    #pragma unroll
                    for (int bj = 0; bj < 2; bj++) {
                        #pragma unroll
                        for (int g = 0; g < 8; g++) {
                            unsigned Bf[4];
                            LDSM4(Bf, bbase + (unsigned)((((kb * 8 + g) * 8) + wn * 2 + bj) << 9));
                            MMA_FP16(C[mi][bj * 2 + 0], Ar[g], Bf[0], Bf[1]);
                            MMA_FP16(C[mi][bj * 2 + 1], Ar[g], Bf[2], Bf[3]);
                        }
                    }
                    if (kb == 1) {
                        // all B reads for this stage are done once mi==3's MMAs are issued:
                        // release the producer BEFORE the last fold
                        if (mi == 3 && lane == 0) MBAR_ARRIVE(sb + SM_FREE + 16 * buf);
                        #pragma unroll
                        for (int nj = 0; nj < 4; nj++)
                            #pragma unroll
                            for (int e = 0; e < 4; e++) {
                                const int rh = e >> 1;
                                float sv = C[mi][nj][e];
                                rmx[mi][rh] = fmaxf(rmx[mi][rh], sv);
                                float ex = ex2f(fmaf(sv, K_EX2A, K_EX2B));  // = e^(10*sv-12)
                                tal[mi][rh] += ex;
                                t1a[mi][rh] = fmaf(ex, (e & 1) ? l1[nj] : l0[nj], t1a[mi][rh]);
                                C[mi][nj][e] = 0.f;
                            }
                    }
                }
            }
        }

        // quad reduce (lanes sharing a row differ in lane&3)
        #pragma unroll
        for (int mi = 0; mi < 4; mi++)
            #pragma unroll
            for (int rh = 0; rh < 2; rh++) {
                #pragma unroll
                for (int off = 1; off <= 2; off <<= 1) {
                    rmx[mi][rh] = fmaxf(rmx[mi][rh], __shfl_xor_sync(0xffffffffu, rmx[mi][rh], off));
                    tal[mi][rh] += __shfl_xor_sync(0xffffffffu, tal[mi][rh], off);
                    t1a[mi][rh] += __shfl_xor_sync(0xffffffffu, t1a[mi][rh], off);
                }
            }
        __syncthreads();   // all warps done reading smem before stats overwrite it
        if ((lane & 3) == 0) {
            float* sred = (float*)(smem + SM_A);
            #pragma unroll
            for (int mi = 0; mi < 4; mi++)
                #pragma unroll
                for (int rh = 0; rh < 2; rh++) {
                    int rr = wm * 64 + mi * 16 + rh * 8 + (lane >> 2);
                    float* p = sred + (wn * 128 + rr) * 4;
                    p[0] = rmx[mi][rh]; p[1] = tal[mi][rh]; p[2] = t1a[mi][rh];
                }
        }
    } else {
        // -------- producer --------
        if (elect_one_pred()) {
            MBAR_EXPECT_TX(sb + SM_AF, ATILE_BYTES);
            BULK_G2S(sb + SM_A, g_Asw[anchor] + (size_t)mtile * ATILE_BYTES,
                     (unsigned)ATILE_BYTES, sb + SM_AF);
            for (int s = 0; s < NSTAGE; s++) {
                const int buf = s & 1;
                if (s >= 2) MBAR_WAIT(sb + SM_FREE + 16 * buf, ((s - 2) >> 1) & 1);
                MBAR_EXPECT_TX(sb + SM_FULL + 16 * buf, BSTAGE_BYTES);
                BULK_G2S(sb + SM_B + (buf << 16), g_Bsw + (size_t)s * BSTAGE_BYTES,
                         (unsigned)BSTAGE_BYTES, sb + SM_FULL + 16 * buf);
            }
        }
        __syncthreads();   // matches consumers' pre-stats barrier
    }

    __syncthreads();
    // per-row loss + in-block masked partial reduction
    float num = 0.f, cnt = 0.f;
    if (tid < MT) {
        const float* sred = (const float*)(smem + SM_A);
        float rmax = -1e30f, tall = 0.f, t1v = 0.f;
        #pragma unroll
        for (int w = 0; w < 4; w++) {
            const float* p = sred + (w * 128 + tid) * 4;
            rmax = fmaxf(rmax, p[0]);
            tall += p[1];
            t1v  += p[2];
        }
        tall -= 64.f * ex2f(K_EX2B);   // remove padded-column contributions (bitwise cancel)
        const int i = mtile * MT + tid;
        if (i < NROWS) {
            float posv = g_pos[i];
            float mfull = fmaxf(rmax * 10.f, posv);
            float tsel = (g_memlab[i] == 0.f) ? t1v : (tall - t1v);
            float epos = __expf(posv - mfull);
            float sum = epos + tsel * __expf(12.f - mfull);
            float lossv = -logf(epos / (sum + 1e-8f) + 1e-8f);
            float q1 = plog1[i], q2 = plog2[i];
            float mask = anchor ? ((q1 > 0.7f && q2 < q1) ? 1.f : 0.f)
                                : ((q2 > 0.7f && q1 < q2) ? 1.f : 0.f);
            num = lossv * mask;
            cnt = mask;
        }
    }
    #pragma unroll
    for (int o = 16; o > 0; o >>= 1) {
        num += __shfl_xor_sync(0xffffffffu, num, o);
        cnt += __shfl_xor_sync(0xffffffffu, cnt, o);
    }
    if (lane == 0) { red2[wid][0] = num; red2[wid][1] = cnt; }
    __syncthreads();
    if (tid == 0) {
        float n = 0.f, c = 0.f;
        #pragma unroll
        for (int w = 0; w < 4; w++) { n += red2[w][0]; c += red2[w][1]; }
        g_part[anchor][mtile] = make_float2(n, c);
    }
}

// ---------------- tiny deterministic final reduction ----------------
__global__ void finalize(float* __restrict__ out) {
    __shared__ float sm[4][2];
    const int t = threadIdx.x;                 // 128 threads
    const int a = t >> 6, idx = t & 63;
    float n = 0.f, c = 0.f;
    if (idx < MTILES) { float2 v = g_part[a][idx]; n = v.x; c = v.y; }
    #pragma unroll
    for (int o = 16; o > 0; o >>= 1) {
        n += __shfl_xor_sync(0xffffffffu, n, o);
        c += __shfl_xor_sync(0xffffffffu, c, o);
    }
    if ((t & 31) == 0) { sm[t >> 5][0] = n; sm[t >> 5][1] = c; }
    __syncthreads();
    if (t == 0) {
        float n1 = sm[0][0] + sm[1][0], c1 = sm[0][1] + sm[1][1];
        float n2 = sm[2][0] + sm[3][0], c2 = sm[2][1] + sm[3][1];
        out[0] = n1 / (c1 + 1e-12f) + n2 / (c2 + 1e-12f);
    }
}

// ---------------- launch ----------------
extern "C" void kernel_launch(void* const* d_in, const int* in_sizes, int n_in,
                              void* d_out, int out_size) {
    const float* feat1 = (const float*)d_in[0];
    const float* feat2 = (const float*)d_in[1];
    const float* ul1   = (const float*)d_in[2];
    const float* ul2   = (const float*)d_in[3];
    const int*   pl1   = (const int*)d_in[4];
    const int*   pl2   = (const int*)d_in[5];
    const float* plog1 = (const float*)d_in[6];
    const float* plog2 = (const float*)d_in[7];
    const int*   sel1  = (const int*)d_in[8];
    const int*   sel2  = (const int*)d_in[9];
    float* out = (float*)d_out;

    cudaFuncSetAttribute(contrast_mm, cudaFuncAttributeMaxDynamicSharedMemorySize, SMEM_TOTAL);

    prep_all<<<4032, 256>>>(feat1, feat2, ul1, ul2, sel1, sel2, pl1, pl2);
    contrast_mm<<<dim3(MTILES, 2), 288, SMEM_TOTAL>>>(plog1, plog2);
    finalize<<<1, 128>>>(out);
}

// round 8
// speedup vs baseline: 11.1206x; 1.0309x over previous
#include <cuda_runtime.h>
#include <cuda_fp16.h>

#define NROWS 8000
#define NPAD  8064
#define CDIM  256
#define HW    1600
#define MT    128
#define MTILES 63
#define NSTAGE 63
#define ATILE_BYTES  65536    // 128 rows x 256 k x 2B fp16, fragment-tiled
#define BSTAGE_BYTES 65536    // 128 cols x 256 k x 2B fp16, fragment-tiled

#define K_EX2A 14.4269504089f    // 10*log2(e)
#define K_EX2B -17.3123404907f   // -12*log2(e)

// ---- dynamic smem map ----
#define SM_AF   0             // A-full barrier
#define SM_FULL 16            // full[s] at +16*s
#define SM_FREE 48            // free[s] at +16*s
#define SM_A    1024          // 65536
#define SM_B    66560         // 2 x 65536
#define SMEM_TOTAL 197632

// ---------------- device scratch ----------------
__device__ __align__(1024) unsigned char g_Asw[2][(size_t)MTILES * ATILE_BYTES];
__device__ __align__(1024) unsigned char g_Bsw[(size_t)NSTAGE * BSTAGE_BYTES];
__device__ float g_memlab[NROWS];
__device__ float g_pos[NROWS];
__device__ float g_alf[2][NPAD];
__device__ float2 g_part[2][MTILES];   // per-(anchor, mtile) masked (sum, count)

// ---------------- PTX helpers ----------------
__device__ __forceinline__ unsigned elect_one_pred() {
    unsigned pred;
    asm volatile("{\n\t.reg .pred p;\n\telect.sync _|p, 0xFFFFFFFF;\n\tselp.b32 %0, 1, 0, p;\n\t}"
                 : "=r"(pred));
    return pred;
}
__device__ __forceinline__ unsigned smem_u32(const void* p) {
    unsigned a;
    asm("{ .reg .u64 t; cvta.to.shared.u64 t, %1; cvt.u32.u64 %0, t; }" : "=r"(a) : "l"(p));
    return a;
}
__device__ __forceinline__ float ex2f(float x) {
    float r;
    asm("ex2.approx.ftz.f32 %0, %1;" : "=f"(r) : "f"(x));
    return r;
}
#define MBAR_INIT(addr, cnt) \
    asm volatile("mbarrier.init.shared.b64 [%0], %1;" :: "r"(addr), "r"(cnt) : "memory")
#define MBAR_EXPECT_TX(addr, bytes) \
    asm volatile("mbarrier.arrive.expect_tx.shared.b64 _, [%0], %1;" :: "r"(addr), "r"(bytes) : "memory")
#define MBAR_ARRIVE(addr) \
    asm volatile("mbarrier.arrive.shared.b64 _, [%0];" :: "r"(addr) : "memory")
#define MBAR_WAIT(addr, ph) do { \
    unsigned _m = (addr), _p = (ph), _d; \
    asm volatile("{\n\t.reg .pred p;\n\tmbarrier.try_wait.parity.acquire.cta.shared::cta.b64 p, [%1], %2;\n\tselp.b32 %0, 1, 0, p;\n\t}" \
                 : "=r"(_d) : "r"(_m), "r"(_p) : "memory"); \
    if (!_d) { \
        asm volatile("{\n\t.reg .pred P1;\n\tWL%=:\n\tmbarrier.try_wait.parity.acquire.cta.shared::cta.b64 P1, [%0], %1, 0x989680;\n\t@P1 bra.uni WD%=;\n\tbra.uni WL%=;\n\tWD%=:\n\t}" \
                     :: "r"(_m), "r"(_p) : "memory"); \
    } } while (0)
#define BULK_G2S(dst, src, bytes, mbar) \
    asm volatile("cp.async.bulk.shared::cluster.global.mbarrier::complete_tx::bytes [%0], [%1], %2, [%3];" \
                 :: "r"(dst), "l"(src), "r"(bytes), "r"(mbar) : "memory")
#define LDSM4(r, addr) \
    asm volatile("ldmatrix.sync.aligned.m8n8.x4.shared.b16 {%0,%1,%2,%3}, [%4];" \
                 : "=r"((r)[0]), "=r"((r)[1]), "=r"((r)[2]), "=r"((r)[3]) : "r"(addr))
#define MMA_FP16(c, a, b0, b1) \
    asm volatile("mma.sync.aligned.m16n8k16.row.col.f32.f16.f16.f32 " \
                 "{%0,%1,%2,%3}, {%4,%5,%6,%7}, {%8,%9}, {%0,%1,%2,%3};" \
                 : "+f"((c)[0]), "+f"((c)[1]), "+f"((c)[2]), "+f"((c)[3]) \
                 : "r"((a)[0]), "r"((a)[1]), "r"((a)[2]), "r"((a)[3]), "r"(b0), "r"(b1))

__device__ __forceinline__ unsigned pack2(float a, float b) {
    __half2 h = __floats2half2_rn(a, b);   // a -> low half (lower address)
    return *(unsigned*)&h;
}

// ---------------- merged prep ----------------
// blocks [0, 2016): feats -> both A tiles (8B stores) + pos dot
// blocks [2016, 4032): gather memory rows -> B stages (8B stores) + labels
__global__ void prep_all(const float* __restrict__ f1, const float* __restrict__ f2,
                         const float* __restrict__ ul1, const float* __restrict__ ul2,
                         const int* __restrict__ sel1, const int* __restrict__ sel2,
                         const int* __restrict__ pl1, const int* __restrict__ pl2) {
    __shared__ float ws[8];
    const int t = threadIdx.x;
    const int r = t >> 6, sub = t & 63;
    const int kc2 = sub & 1, kh = (sub >> 1) & 1, kt = sub >> 2;
    const int k0 = kt * 16 + kh * 8 + kc2 * 4;

    if (blockIdx.x < 2016) {
        // ---- feats ----
        const int i = blockIdx.x * 4 + r;
        float4 x1 = make_float4(0.f, 0.f, 0.f, 0.f), x2 = x1;
        if (i < NROWS) {
            x1 = *(const float4*)(f1 + i * CDIM + k0);
            x2 = *(const float4*)(f2 + i * CDIM + k0);
        }
        const int tile = i >> 7, m = i & 127;
        const int mt = m >> 4, mi8 = (m >> 3) & 1, mr = m & 7;
        const int q = kh * 2 + mi8;
        const unsigned off = (unsigned)(((kt * 8 + mt) << 9) + (q << 7) + (mr << 4) + kc2 * 8);
        uint2 u1 = make_uint2(pack2(x1.x, x1.y), pack2(x1.z, x1.w));
        uint2 u2 = make_uint2(pack2(x2.x, x2.y), pack2(x2.z, x2.w));
        *(uint2*)(g_Asw[0] + (size_t)tile * ATILE_BYTES + off) = u1;
        *(uint2*)(g_Asw[1] + (size_t)tile * ATILE_BYTES + off) = u2;
        // pos dot (exact fp32)
        float p = x1.x * x2.x + x1.y * x2.y + x1.z * x2.z + x1.w * x2.w;
        #pragma unroll
        for (int o = 16; o > 0; o >>= 1) p += __shfl_xor_sync(0xffffffffu, p, o);
        if ((t & 31) == 0) ws[t >> 5] = p;
        __syncthreads();
        if (sub == 0 && i < NROWS)
            g_pos[i] = (ws[r * 2] + ws[r * 2 + 1]) * 10.f;
    } else {
        // ---- gather ----
        const int j = (blockIdx.x - 2016) * 4 + r;
        float x0 = 0.f, xa = 0.f, xb = 0.f, xc = 0.f;
        if (j < NROWS) {
            int n; const float* ul; const int* pl;
            if (j < 4000) { n = sel1[j];        ul = ul1; pl = pl1; }
            else          { n = sel2[j - 4000]; ul = ul2; pl = pl2; }
            const int b = n / HW, hw = n - b * HW;
            const float* src = ul + (size_t)(b * CDIM + k0) * HW + hw;
            x0 = src[0]; xa = src[HW]; xb = src[2 * HW]; xc = src[3 * HW];
            if (sub == 0) g_memlab[j] = (float)pl[n];
        }
        if (sub == 1) {   // anchor labels (padded -> 0)
            g_alf[0][j] = (j < NROWS) ? (float)pl1[j] : 0.f;
            g_alf[1][j] = (j < NROWS) ? (float)pl2[j] : 0.f;
        }
        const int chunk = j >> 7, nn = j & 127;
        const int nt = nn >> 4, ni8 = (nn >> 3) & 1, nr = nn & 7;
        const int q = ni8 * 2 + kh;
        const unsigned off = (unsigned)(((kt * 8 + nt) << 9) + (q << 7) + (nr << 4) + kc2 * 8);
        *(uint2*)(g_Bsw + (size_t)chunk * BSTAGE_BYTES + off) =
            make_uint2(pack2(x0, xa), pack2(xb, xc));
    }
}

// ---------------- main: fp16 mma.sync GEMM, 4Mx2N warps, B-reuse loop order ----------------
// grid (63, 2), 288 threads: warps 0-7 = consumers (warp tile 32x64), warp 8 = producer.
__global__ __launch_bounds__(288, 1) void contrast_mm(const float* __restrict__ plog1,
                                                      const float* __restrict__ plog2) {
    extern __shared__ char smem[];
    __shared__ float red2[9][2];
    const unsigned sb = smem_u32(smem);
    const int tid = threadIdx.x, wid = tid >> 5, lane = tid & 31;
    const int mtile = blockIdx.x, anchor = blockIdx.y;

    if (tid == 0) {
        MBAR_INIT(sb + SM_AF, 1);
        MBAR_INIT(sb + SM_FULL + 0, 1);  MBAR_INIT(sb + SM_FULL + 16, 1);
        MBAR_INIT(sb + SM_FREE + 0, 8);  MBAR_INIT(sb + SM_FREE + 16, 8);
    }
    __syncthreads();

    if (wid < 8) {
        // -------- consumer: 4 M-warps x 2 N-warps, warp tile 32(M) x 64(N) --------
        const int wm = wid >> 1, wn = wid & 1;
        const unsigned lanoff = (unsigned)(((lane >> 3) << 7) + ((lane & 7) << 4));
        const unsigned abase = sb + SM_A + lanoff;
        const float* __restrict__ labf = g_alf[anchor];

        float C[2][8][4];                 // [mi][n8 block][elem]
        #pragma unroll
        for (int mi = 0; mi < 2; mi++)
            #pragma unroll
            for (int nj = 0; nj < 8; nj++)
                #pragma unroll
                for (int e = 0; e < 4; e++) C[mi][nj][e] = 0.f;
        float rmx[2][2], tal[2][2], t1a[2][2];
        #pragma unroll
        for (int mi = 0; mi < 2; mi++)
            #pragma unroll
            for (int rh = 0; rh < 2; rh++) { rmx[mi][rh] = -1e30f; tal[mi][rh] = 0.f; t1a[mi][rh] = 0.f; }

        MBAR_WAIT(sb + SM_AF, 0);   // A tile resident

        for (int s = 0; s < NSTAGE; s++) {
            const int buf = s & 1;
            MBAR_WAIT(sb + SM_FULL + 16 * buf, (s >> 1) & 1);
            const unsigned bbase = sb + SM_B + (buf << 16) + lanoff;

            // stage labels for this warp's 64 columns
            const int cb = s * 128 + wn * 64 + ((lane & 3) << 1);
            float l0[8], l1[8];
            #pragma unroll
            for (int nj = 0; nj < 8; nj++) {
                l0[nj] = labf[cb + nj * 8];
                l1[nj] = labf[cb + nj * 8 + 1];
            }

            #pragma unroll
            for (int kt = 0; kt < 16; kt++) {
                unsigned Ar[2][4], Bf[4][4];
                #pragma unroll
                for (int mi = 0; mi < 2; mi++)
                    LDSM4(Ar[mi], abase + (unsigned)((kt * 8 + wm * 2 + mi) << 9));
                #pragma unroll
                for (int t = 0; t < 4; t++)
                    LDSM4(Bf[t], bbase + (unsigned)((kt * 8 + wn * 4 + t) << 9));
                #pragma unroll
                for (int mi = 0; mi < 2; mi++)
                    #pragma unroll
                    for (int t = 0; t < 4; t++) {
                        MMA_FP16(C[mi][t * 2 + 0], Ar[mi], Bf[t][0], Bf[t][1]);
                        MMA_FP16(C[mi][t * 2 + 1], Ar[mi], Bf[t][2], Bf[t][3]);
                    }
            }
            // all B uses issued -> release producer, then fold (drains behind queued MMAs)
            if (lane == 0) MBAR_ARRIVE(sb + SM_FREE + 16 * buf);
            #pragma unroll
            for (int mi = 0; mi < 2; mi++)
                #pragma unroll
                for (int nj = 0; nj < 8; nj++)
                    #pragma unroll
                    for (int e = 0; e < 4; e++) {
                        const int rh = e >> 1;
                        float sv = C[mi][nj][e];
                        rmx[mi][rh] = fmaxf(rmx[mi][rh], sv);
                        float ex = ex2f(fmaf(sv, K_EX2A, K_EX2B));  // = e^(10*sv-12)
                        tal[mi][rh] += ex;
                        t1a[mi][rh] = fmaf(ex, (e & 1) ? l1[nj] : l0[nj], t1a[mi][rh]);
                        C[mi][nj][e] = 0.f;
                    }
        }

        // quad reduce (lanes sharing a row differ in lane&3)
        #pragma unroll
        for (int mi = 0; mi < 2; mi++)
            #pragma unroll
            for (int rh = 0; rh < 2; rh++) {
                #pragma unroll
                for (int off = 1; off <= 2; off <<= 1) {
                    rmx[mi][rh] = fmaxf(rmx[mi][rh], __shfl_xor_sync(0xffffffffu, rmx[mi][rh], off));
                    tal[mi][rh] += __shfl_xor_sync(0xffffffffu, tal[mi][rh], off);
                    t1a[mi][rh] += __shfl_xor_sync(0xffffffffu, t1a[mi][rh], off);
                }
            }
        __syncthreads();   // all warps done reading smem before stats overwrite it
        if ((lane & 3) == 0) {
            float* sred = (float*)(smem + SM_A);
            #pragma unroll
            for (int mi = 0; mi < 2; mi++)
                #pragma unroll
                for (int rh = 0; rh < 2; rh++) {
                    int rr = wm * 32 + mi * 16 + rh * 8 + (lane >> 2);
                    float* p = sred + (wn * 128 + rr) * 4;
                    p[0] = rmx[mi][rh]; p[1] = tal[mi][rh]; p[2] = t1a[mi][rh];
                }
        }
    } else {
        // -------- producer --------
        if (elect_one_pred()) {
            MBAR_EXPECT_TX(sb + SM_AF, ATILE_BYTES);
            BULK_G2S(sb + SM_A, g_Asw[anchor] + (size_t)mtile * ATILE_BYTES,
                     (unsigned)ATILE_BYTES, sb + SM_AF);
            for (int s = 0; s < NSTAGE; s++) {
                const int buf = s & 1;
                if (s >= 2) MBAR_WAIT(sb + SM_FREE + 16 * buf, ((s - 2) >> 1) & 1);
                MBAR_EXPECT_TX(sb + SM_FULL + 16 * buf, BSTAGE_BYTES);
                BULK_G2S(sb + SM_B + (buf << 16), g_Bsw + (size_t)s * BSTAGE_BYTES,
                         (unsigned)BSTAGE_BYTES, sb + SM_FULL + 16 * buf);
            }
        }
        __syncthreads();   // matches consumers' pre-stats barrier
    }

    __syncthreads();
    // per-row loss + in-block masked partial reduction
    float num = 0.f, cnt = 0.f;
    if (tid < MT) {
        const float* sred = (const float*)(smem + SM_A);
        float rmax = -1e30f, tall = 0.f, t1v = 0.f;
        #pragma unroll
        for (int w = 0; w < 2; w++) {
            const float* p = sred + (w * 128 + tid) * 4;
            rmax = fmaxf(rmax, p[0]);
            tall += p[1];
            t1v  += p[2];
        }
        tall -= 64.f * ex2f(K_EX2B);   // remove padded-column contributions (bitwise cancel)
        const int i = mtile * MT + tid;
        if (i < NROWS) {
            float posv = g_pos[i];
            float mfull = fmaxf(rmax * 10.f, posv);
            float tsel = (g_memlab[i] == 0.f) ? t1v : (tall - t1v);
            float epos = __expf(posv - mfull);
            float sum = epos + tsel * __expf(12.f - mfull);
            float lossv = -logf(epos / (sum + 1e-8f) + 1e-8f);
            float q1 = plog1[i], q2 = plog2[i];
            float mask = anchor ? ((q1 > 0.7f && q2 < q1) ? 1.f : 0.f)
                                : ((q2 > 0.7f && q1 < q2) ? 1.f : 0.f);
            num = lossv * mask;
            cnt = mask;
        }
    }
    #pragma unroll
    for (int o = 16; o > 0; o >>= 1) {
        num += __shfl_xor_sync(0xffffffffu, num, o);
        cnt += __shfl_xor_sync(0xffffffffu, cnt, o);
    }
    if (lane == 0) { red2[wid][0] = num; red2[wid][1] = cnt; }
    __syncthreads();
    if (tid == 0) {
        float n = 0.f, c = 0.f;
        #pragma unroll
        for (int w = 0; w < 4; w++) { n += red2[w][0]; c += red2[w][1]; }
        g_part[anchor][mtile] = make_float2(n, c);
    }
}

// ---------------- tiny deterministic final reduction ----------------
__global__ void finalize(float* __restrict__ out) {
    __shared__ float sm[4][2];
    const int t = threadIdx.x;                 // 128 threads
    const int a = t >> 6, idx = t & 63;
    float n = 0.f, c = 0.f;
    if (idx < MTILES) { float2 v = g_part[a][idx]; n = v.x; c = v.y; }
    #pragma unroll
    for (int o = 16; o > 0; o >>= 1) {
        n += __shfl_xor_sync(0xffffffffu, n, o);
        c += __shfl_xor_sync(0xffffffffu, c, o);
    }
    if ((t & 31) == 0) { sm[t >> 5][0] = n; sm[t >> 5][1] = c; }
    __syncthreads();
    if (t == 0) {
        float n1 = sm[0][0] + sm[1][0], c1 = sm[0][1] + sm[1][1];
        float n2 = sm[2][0] + sm[3][0], c2 = sm[2][1] + sm[3][1];
        out[0] = n1 / (c1 + 1e-12f) + n2 / (c2 + 1e-12f);
    }
}

// ---------------- launch ----------------
extern "C" void kernel_launch(void* const* d_in, const int* in_sizes, int n_in,
                              void* d_out, int out_size) {
    const float* feat1 = (const float*)d_in[0];
    const float* feat2 = (const float*)d_in[1];
    const float* ul1   = (const float*)d_in[2];
    const float* ul2   = (const float*)d_in[3];
    const int*   pl1   = (const int*)d_in[4];
    const int*   pl2   = (const int*)d_in[5];
    const float* plog1 = (const float*)d_in[6];
    const float* plog2 = (const float*)d_in[7];
    const int*   sel1  = (const int*)d_in[8];
    const int*   sel2  = (const int*)d_in[9];
    float* out = (float*)d_out;

    cudaFuncSetAttribute(contrast_mm, cudaFuncAttributeMaxDynamicSharedMemorySize, SMEM_TOTAL);

    prep_all<<<4032, 256>>>(feat1, feat2, ul1, ul2, sel1, sel2, pl1, pl2);
    contrast_mm<<<dim3(MTILES, 2), 288, SMEM_TOTAL>>>(plog1, plog2);
    finalize<<<1, 128>>>(out);
}

// round 10
// speedup vs baseline: 11.7629x; 1.0578x over previous
#include <cuda_runtime.h>
#include <cuda_fp16.h>

#define NROWS 8000
#define NPADM 8064            // padded M (63 x 128)
#define NPADN 8192            // padded N (64 x 128)
#define CDIM  256
#define HW    1600
#define MT    128
#define MTILES 63
#define NSTAGE 64
#define ATILE_BYTES  65536    // 128 rows x 256 k x 2B fp16, fragment-tiled
#define BSTAGE_BYTES 65536    // 128 cols x 256 k x 2B fp16, fragment-tiled
#define LAB_BYTES    32768    // 8192 floats

#define K_EX2A 14.4269504089f    // 10*log2(e)
#define K_EX2B -17.3123404907f   // -12*log2(e)

// ---- dynamic smem map (total 230400 <= 232448) ----
#define SM_AF   0             // A+labels full barrier
#define SM_FULL 16            // full[s] at +16*s
#define SM_FREE 48            // free[s] at +16*s
#define SM_LAB  1024          // 32768 (anchor labels, f32)
#define SM_A    33792         // 65536
#define SM_B    99328         // 2 x 65536
#define SMEM_TOTAL 230400

// ---------------- device scratch ----------------
__device__ __align__(1024) unsigned char g_Asw[2][(size_t)MTILES * ATILE_BYTES];
__device__ __align__(1024) unsigned char g_Bsw[(size_t)NSTAGE * BSTAGE_BYTES];
__device__ float g_memlab[NROWS];
__device__ float g_pos[NROWS];
__device__ __align__(1024) float g_alf[2][NPADN];
__device__ float2 g_part[2][MTILES];   // per-(anchor, mtile) masked (sum, count)

// ---------------- PTX helpers ----------------
__device__ __forceinline__ unsigned smem_u32(const void* p) {
    unsigned a;
    asm("{ .reg .u64 t; cvta.to.shared.u64 t, %1; cvt.u32.u64 %0, t; }" : "=r"(a) : "l"(p));
    return a;
}
__device__ __forceinline__ float ex2f(float x) {
    float r;
    asm("ex2.approx.ftz.f32 %0, %1;" : "=f"(r) : "f"(x));
    return r;
}
#define MBAR_INIT(addr, cnt) \
    asm volatile("mbarrier.init.shared.b64 [%0], %1;" :: "r"(addr), "r"(cnt) : "memory")
#define MBAR_EXPECT_TX(addr, bytes) \
    asm volatile("mbarrier.arrive.expect_tx.shared.b64 _, [%0], %1;" :: "r"(addr), "r"(bytes) : "memory")
#define MBAR_ARRIVE(addr) \
    asm volatile("mbarrier.arrive.shared.b64 _, [%0];" :: "r"(addr) : "memory")
#define MBAR_WAIT(addr, ph) do { \
    unsigned _m = (addr), _p = (ph), _d; \
    asm volatile("{\n\t.reg .pred p;\n\tmbarrier.try_wait.parity.acquire.cta.shared::cta.b64 p, [%1], %2;\n\tselp.b32 %0, 1, 0, p;\n\t}" \
                 : "=r"(_d) : "r"(_m), "r"(_p) : "memory"); \
    if (!_d) { \
        asm volatile("{\n\t.reg .pred P1;\n\tWL%=:\n\tmbarrier.try_wait.parity.acquire.cta.shared::cta.b64 P1, [%0], %1, 0x989680;\n\t@P1 bra.uni WD%=;\n\tbra.uni WL%=;\n\tWD%=:\n\t}" \
                     :: "r"(_m), "r"(_p) : "memory"); \
    } } while (0)
#define BULK_G2S(dst, src, bytes, mbar) \
    asm volatile("cp.async.bulk.shared::cluster.global.mbarrier::complete_tx::bytes [%0], [%1], %2, [%3];" \
                 :: "r"(dst), "l"(src), "r"(bytes), "r"(mbar) : "memory")
#define LDSM4(r, addr) \
    asm volatile("ldmatrix.sync.aligned.m8n8.x4.shared.b16 {%0,%1,%2,%3}, [%4];" \
                 : "=r"((r)[0]), "=r"((r)[1]), "=r"((r)[2]), "=r"((r)[3]) : "r"(addr))
#define MMA_FP16(c, a, b0, b1) \
    asm volatile("mma.sync.aligned.m16n8k16.row.col.f32.f16.f16.f32 " \
                 "{%0,%1,%2,%3}, {%4,%5,%6,%7}, {%8,%9}, {%0,%1,%2,%3};" \
                 : "+f"((c)[0]), "+f"((c)[1]), "+f"((c)[2]), "+f"((c)[3]) \
                 : "r"((a)[0]), "r"((a)[1]), "r"((a)[2]), "r"((a)[3]), "r"(b0), "r"(b1))

__device__ __forceinline__ unsigned pack2(float a, float b) {
    __half2 h = __floats2half2_rn(a, b);   // a -> low half (lower address)
    return *(unsigned*)&h;
}

// ---------------- merged prep ----------------
// blocks [0, 2016): feats -> both A tiles (8B stores) + pos dot
// blocks [2016, 4064): gather memory rows -> B stages (8B stores) + labels
__global__ void prep_all(const float* __restrict__ f1, const float* __restrict__ f2,
                         const float* __restrict__ ul1, const float* __restrict__ ul2,
                         const int* __restrict__ sel1, const int* __restrict__ sel2,
                         const int* __restrict__ pl1, const int* __restrict__ pl2) {
    __shared__ float ws[8];
    const int t = threadIdx.x;
    const int r = t >> 6, sub = t & 63;
    const int kc2 = sub & 1, kh = (sub >> 1) & 1, kt = sub >> 2;
    const int k0 = kt * 16 + kh * 8 + kc2 * 4;

    if (blockIdx.x < 2016) {
        // ---- feats ----
        const int i = blockIdx.x * 4 + r;
        float4 x1 = make_float4(0.f, 0.f, 0.f, 0.f), x2 = x1;
        if (i < NROWS) {
            x1 = *(const float4*)(f1 + i * CDIM + k0);
            x2 = *(const float4*)(f2 + i * CDIM + k0);
        }
        const int tile = i >> 7, m = i & 127;
        const int mt = m >> 4, mi8 = (m >> 3) & 1, mr = m & 7;
        const int q = kh * 2 + mi8;
        const unsigned off = (unsigned)(((kt * 8 + mt) << 9) + (q << 7) + (mr << 4) + kc2 * 8);
        uint2 u1 = make_uint2(pack2(x1.x, x1.y), pack2(x1.z, x1.w));
        uint2 u2 = make_uint2(pack2(x2.x, x2.y), pack2(x2.z, x2.w));
        *(uint2*)(g_Asw[0] + (size_t)tile * ATILE_BYTES + off) = u1;
        *(uint2*)(g_Asw[1] + (size_t)tile * ATILE_BYTES + off) = u2;
        // pos dot (exact fp32)
        float p = x1.x * x2.x + x1.y * x2.y + x1.z * x2.z + x1.w * x2.w;
        #pragma unroll
        for (int o = 16; o > 0; o >>= 1) p += __shfl_xor_sync(0xffffffffu, p, o);
        if ((t & 31) == 0) ws[t >> 5] = p;
        __syncthreads();
        if (sub == 0 && i < NROWS)
            g_pos[i] = (ws[r * 2] + ws[r * 2 + 1]) * 10.f;
    } else {
        // ---- gather ----
        const int j = (blockIdx.x - 2016) * 4 + r;   // j < 8192
        float x0 = 0.f, xa = 0.f, xb = 0.f, xc = 0.f;
        if (j < NROWS) {
            int n; const float* ul; const int* pl;
            if (j < 4000) { n = sel1[j];        ul = ul1; pl = pl1; }
            else          { n = sel2[j - 4000]; ul = ul2; pl = pl2; }
            const int b = n / HW, hw = n - b * HW;
            const float* src = ul + (size_t)(b * CDIM + k0) * HW + hw;
            x0 = src[0]; xa = src[HW]; xb = src[2 * HW]; xc = src[3 * HW];
            if (sub == 0) g_memlab[j] = (float)pl[n];
        }
        if (sub == 1) {   // anchor labels (padded -> 0)
            g_alf[0][j] = (j < NROWS) ? (float)pl1[j] : 0.f;
            g_alf[1][j] = (j < NROWS) ? (float)pl2[j] : 0.f;
        }
        const int chunk = j >> 7, nn = j & 127;
        const int nt = nn >> 4, ni8 = (nn >> 3) & 1, nr = nn & 7;
        const int q = ni8 * 2 + kh;
        const unsigned off = (unsigned)(((kt * 8 + nt) << 9) + (q << 7) + (nr << 4) + kc2 * 8);
        *(uint2*)(g_Bsw + (size_t)chunk * BSTAGE_BYTES + off) =
            make_uint2(pack2(x0, xa), pack2(xb, xc));
    }
}

// ---------------- fold one element of the PREVIOUS stage's scores ----------------
// f must be a compile-time constant (unrolled caller) so C stays in registers.
#define FOLD1(Cp, f, ps) do { \
    const int mi_ = (f) >> 4, nj_ = ((f) >> 2) & 3, e_ = (f) & 3; \
    const int rh_ = e_ >> 1; \
    float sv_ = Cp[mi_][nj_][e_]; \
    float lb_; \
    asm volatile("ld.shared.f32 %0, [%1];" : "=f"(lb_) \
        : "r"(sb + SM_LAB + (unsigned)(((unsigned)(ps) * 128u + wn * 32u + nj_ * 8u + ((lane & 3) << 1) + (e_ & 1)) << 2))); \
    rmx[mi_][rh_] = fmaxf(rmx[mi_][rh_], sv_); \
    float ex_ = ex2f(fmaf(sv_, K_EX2A, K_EX2B)); \
    tal[mi_][rh_] += ex_; \
    t1a[mi_][rh_] = fmaf(ex_, lb_, t1a[mi_][rh_]); \
    Cp[mi_][nj_][e_] = 0.f; \
} while (0)

// one stage: producer prefetch (warp0 lane0) + 16 kt of MMA + interleaved fold of prev C
#define STAGE(t, Ccur, Cprv, DOFOLD) do { \
    const int buf_ = (t) & 1; \
    if (wid == 0 && lane == 0) { \
        const int nt_ = (t) + 1; \
        if (nt_ < NSTAGE) { \
            if (nt_ >= 2) MBAR_WAIT(sb + SM_FREE + 16 * (nt_ & 1), ((nt_ - 2) >> 1) & 1); \
            MBAR_EXPECT_TX(sb + SM_FULL + 16 * (nt_ & 1), BSTAGE_BYTES); \
            BULK_G2S(sb + SM_B + ((unsigned)(nt_ & 1) << 16), \
                     g_Bsw + (size_t)nt_ * BSTAGE_BYTES, (unsigned)BSTAGE_BYTES, \
                     sb + SM_FULL + 16 * (nt_ & 1)); \
        } \
    } \
    MBAR_WAIT(sb + SM_FULL + 16 * buf_, ((t) >> 1) & 1); \
    const unsigned bbase_ = sb + SM_B + ((unsigned)buf_ << 16) + lanoff; \
    _Pragma("unroll") \
    for (int kt_ = 0; kt_ < 16; kt_++) { \
        unsigned Ar0[4], Ar1[4], Bf0[4], Bf1[4]; \
        LDSM4(Ar0, abase  + (unsigned)((kt_ * 8 + wm * 2 + 0) << 9)); \
        LDSM4(Ar1, abase  + (unsigned)((kt_ * 8 + wm * 2 + 1) << 9)); \
        LDSM4(Bf0, bbase_ + (unsigned)((kt_ * 8 + wn * 2 + 0) << 9)); \
        LDSM4(Bf1, bbase_ + (unsigned)((kt_ * 8 + wn * 2 + 1) << 9)); \
        MMA_FP16(Ccur[0][0], Ar0, Bf0[0], Bf0[1]); \
        MMA_FP16(Ccur[0][1], Ar0, Bf0[2], Bf0[3]); \
        MMA_FP16(Ccur[0][2], Ar0, Bf1[0], Bf1[1]); \
        MMA_FP16(Ccur[0][3], Ar0, Bf1[2], Bf1[3]); \
        MMA_FP16(Ccur[1][0], Ar1, Bf0[0], Bf0[1]); \
        MMA_FP16(Ccur[1][1], Ar1, Bf0[2], Bf0[3]); \
        MMA_FP16(Ccur[1][2], Ar1, Bf1[0], Bf1[1]); \
        MMA_FP16(Ccur[1][3], Ar1, Bf1[2], Bf1[3]); \
        if (DOFOLD) { \
            FOLD1(Cprv, kt_ * 2 + 0, (t) - 1); \
            FOLD1(Cprv, kt_ * 2 + 1, (t) - 1); \
        } \
    } \
    if (lane == 0) MBAR_ARRIVE(sb + SM_FREE + 16 * buf_); \
} while (0)

// ---------------- main: fp16 mma.sync GEMM, 16 warps (4Mx4N, 32x32), deferred fold ----------------
__global__ __launch_bounds__(512, 1) void contrast_mm(const float* __restrict__ plog1,
                                                      const float* __restrict__ plog2) {
    extern __shared__ char smem[];
    const unsigned sb = smem_u32(smem);
    const int tid = threadIdx.x, wid = tid >> 5, lane = tid & 31;
    const int mtile = blockIdx.x, anchor = blockIdx.y;

    if (tid == 0) {
        MBAR_INIT(sb + SM_AF, 1);
        MBAR_INIT(sb + SM_FULL + 0, 1);   MBAR_INIT(sb + SM_FULL + 16, 1);
        MBAR_INIT(sb + SM_FREE + 0, 16);  MBAR_INIT(sb + SM_FREE + 16, 16);
    }
    __syncthreads();
    if (tid == 0) {
        // A tile + labels (one barrier, combined tx), and stage 0 of B
        MBAR_EXPECT_TX(sb + SM_AF, ATILE_BYTES + LAB_BYTES);
        BULK_G2S(sb + SM_A,   g_Asw[anchor] + (size_t)mtile * ATILE_BYTES, (unsigned)ATILE_BYTES, sb + SM_AF);
        BULK_G2S(sb + SM_LAB, g_alf[anchor], (unsigned)LAB_BYTES, sb + SM_AF);
        MBAR_EXPECT_TX(sb + SM_FULL + 0, BSTAGE_BYTES);
        BULK_G2S(sb + SM_B, g_Bsw, (unsigned)BSTAGE_BYTES, sb + SM_FULL + 0);
    }

    const int wm = wid >> 2, wn = wid & 3;   // 4 M-warps x 4 N-warps, tile 32x32
    const unsigned lanoff = (unsigned)(((lane >> 3) << 7) + ((lane & 7) << 4));
    const unsigned abase = sb + SM_A + lanoff;

    float Ca[2][4][4], Cb[2][4][4];
    #pragma unroll
    for (int mi = 0; mi < 2; mi++)
        #pragma unroll
        for (int nj = 0; nj < 4; nj++)
            #pragma unroll
            for (int e = 0; e < 4; e++) { Ca[mi][nj][e] = 0.f; Cb[mi][nj][e] = 0.f; }
    float rmx[2][2], tal[2][2], t1a[2][2];
    #pragma unroll
    for (int mi = 0; mi < 2; mi++)
        #pragma unroll
        for (int rh = 0; rh < 2; rh++) { rmx[mi][rh] = -1e30f; tal[mi][rh] = 0.f; t1a[mi][rh] = 0.f; }

    MBAR_WAIT(sb + SM_AF, 0);   // A tile + labels resident

    for (int sp = 0; sp < NSTAGE / 2; sp++) {
        STAGE(2 * sp,     Ca, Cb, sp > 0);   // fold stage 2sp-1 (in Cb)
        STAGE(2 * sp + 1, Cb, Ca, true);     // fold stage 2sp   (in Ca)
    }
    // fold the final stage (63, in Cb)
    #pragma unroll
    for (int f = 0; f < 32; f++) FOLD1(Cb, f, NSTAGE - 1);

    // quad reduce (lanes sharing a row differ in lane&3)
    #pragma unroll
    for (int mi = 0; mi < 2; mi++)
        #pragma unroll
        for (int rh = 0; rh < 2; rh++) {
            #pragma unroll
            for (int off = 1; off <= 2; off <<= 1) {
                rmx[mi][rh] = fmaxf(rmx[mi][rh], __shfl_xor_sync(0xffffffffu, rmx[mi][rh], off));
                tal[mi][rh] += __shfl_xor_sync(0xffffffffu, tal[mi][rh], off);
                t1a[mi][rh] += __shfl_xor_sync(0xffffffffu, t1a[mi][rh], off);
            }
        }
    __syncthreads();   // all warps done reading A smem before stats overwrite it
    if ((lane & 3) == 0) {
        float* sred = (float*)(smem + SM_A);
        #pragma unroll
        for (int mi = 0; mi < 2; mi++)
            #pragma unroll
            for (int rh = 0; rh < 2; rh++) {
                int rr = wm * 32 + mi * 16 + rh * 8 + (lane >> 2);
                float* p = sred + (wn * 128 + rr) * 4;
                p[0] = rmx[mi][rh]; p[1] = tal[mi][rh]; p[2] = t1a[mi][rh];
            }
    }

    __syncthreads();
    // per-row loss + in-block masked partial reduction
    float num = 0.f, cnt = 0.f;
    if (tid < MT) {
        const float* sred = (const float*)(smem + SM_A);
        float rmax = -1e30f, tall = 0.f, t1v = 0.f;
        #pragma unroll
        for (int w = 0; w < 4; w++) {
            const float* p = sred + (w * 128 + tid) * 4;
            rmax = fmaxf(rmax, p[0]);
            tall += p[1];
            t1v  += p[2];
        }
        tall -= (float)(NPADN - NROWS) * ex2f(K_EX2B);   // remove padded-column contributions
        const int i = mtile * MT + tid;
        if (i < NROWS) {
            float posv = g_pos[i];
            float mfull = fmaxf(rmax * 10.f, posv);
            float tsel = (g_memlab[i] == 0.f) ? t1v : (tall - t1v);
            float epos = __expf(posv - mfull);
            float sum = epos + tsel * __expf(12.f - mfull);
            float lossv = -logf(epos / (sum + 1e-8f) + 1e-8f);
            float q1 = plog1[i], q2 = plog2[i];
            float mask = anchor ? ((q1 > 0.7f && q2 < q1) ? 1.f : 0.f)
                                : ((q2 > 0.7f && q1 < q2) ? 1.f : 0.f);
            num = lossv * mask;
            cnt = mask;
        }
    }
    #pragma unroll
    for (int o = 16; o > 0; o >>= 1) {
        num += __shfl_xor_sync(0xffffffffu, num, o);
        cnt += __shfl_xor_sync(0xffffffffu, cnt, o);
    }
    float* red2 = (float*)(smem + SM_LAB);   // labels dead by now
    if (lane == 0 && tid < MT) { red2[wid * 2] = num; red2[wid * 2 + 1] = cnt; }
    __syncthreads();
    if (tid == 0) {
        float n = 0.f, c = 0.f;
        #pragma unroll
        for (int w = 0; w < 4; w++) { n += red2[w * 2]; c += red2[w * 2 + 1]; }
        g_part[anchor][mtile] = make_float2(n, c);
    }
}

// ---------------- tiny deterministic final reduction ----------------
__global__ void finalize(float* __restrict__ out) {
    __shared__ float sm[4][2];
    const int t = threadIdx.x;                 // 128 threads
    const int a = t >> 6, idx = t & 63;
    float n = 0.f, c = 0.f;
    if (idx < MTILES) { float2 v = g_part[a][idx]; n = v.x; c = v.y; }
    #pragma unroll
    for (int o = 16; o > 0; o >>= 1) {
        n += __shfl_xor_sync(0xffffffffu, n, o);
        c += __shfl_xor_sync(0xffffffffu, c, o);
    }
    if ((t & 31) == 0) { sm[t >> 5][0] = n; sm[t >> 5][1] = c; }
    __syncthreads();
    if (t == 0) {
        float n1 = sm[0][0] + sm[1][0], c1 = sm[0][1] + sm[1][1];
        float n2 = sm[2][0] + sm[3][0], c2 = sm[2][1] + sm[3][1];
        out[0] = n1 / (c1 + 1e-12f) + n2 / (c2 + 1e-12f);
    }
}

// ---------------- launch ----------------
extern "C" void kernel_launch(void* const* d_in, const int* in_sizes, int n_in,
                              void* d_out, int out_size) {
    const float* feat1 = (const float*)d_in[0];
    const float* feat2 = (const float*)d_in[1];
    const float* ul1   = (const float*)d_in[2];
    const float* ul2   = (const float*)d_in[3];
    const int*   pl1   = (const int*)d_in[4];
    const int*   pl2   = (const int*)d_in[5];
    const float* plog1 = (const float*)d_in[6];
    const float* plog2 = (const float*)d_in[7];
    const int*   sel1  = (const int*)d_in[8];
    const int*   sel2  = (const int*)d_in[9];
    float* out = (float*)d_out;

    cudaFuncSetAttribute(contrast_mm, cudaFuncAttributeMaxDynamicSharedMemorySize, SMEM_TOTAL);

    prep_all<<<4064, 256>>>(feat1, feat2, ul1, ul2, sel1, sel2, pl1, pl2);
    contrast_mm<<<dim3(MTILES, 2), 512, SMEM_TOTAL>>>(plog1, plog2);
    finalize<<<1, 128>>>(out);
}

// round 12
// speedup vs baseline: 12.7310x; 1.0823x over previous
#include <cuda_runtime.h>
#include <cuda_fp16.h>

#define NROWS 8000
#define NPADN 8192            // padded N (64 x 128)
#define CDIM  256
#define HW    1600
#define MT    128
#define MTILES 63
#define NSTAGE 64
#define NJOBS  1008           // 2 anchors x 63 mtiles x 8 chunks
#define GRIDC  148
#define ATILE_BYTES  65536    // 128 rows x 256 k x 2B fp16, fragment-tiled
#define BSTAGE_BYTES 65536    // 128 cols x 256 k x 2B fp16, fragment-tiled
#define LAB_BYTES    32768    // 8192 floats

#define K_EX2A 14.4269504089f    // 10*log2(e)
#define K_EX2B -17.3123404907f   // -12*log2(e)

// ---- dynamic smem map (total 230400 <= 232448) ----
#define SM_AF   0             // A(+labels) full barrier
#define SM_FULL 16            // full[s] at +16*s
#define SM_FREE 48            // free[s] at +16*s
#define SM_LAB  1024          // 32768 (anchor labels, f32)
#define SM_A    33792         // 65536
#define SM_B    99328         // 2 x 65536
#define SMEM_TOTAL 230400

// ---------------- device scratch ----------------
__device__ __align__(1024) unsigned char g_Asw[2][(size_t)MTILES * ATILE_BYTES];
__device__ __align__(1024) unsigned char g_Bsw[(size_t)NSTAGE * BSTAGE_BYTES];
__device__ float g_memlab[NROWS];
__device__ float g_pos[NROWS];
__device__ __align__(1024) float g_alf[2][NPADN];
__device__ float4 g_jpart[(size_t)NJOBS * 4 * 128];   // per (job, wn, row): rmax, tall, t1, pad
__device__ float2 g_part[2][MTILES];                  // per-(anchor, mtile) masked (sum, count)

// ---------------- PTX helpers ----------------
__device__ __forceinline__ unsigned smem_u32(const void* p) {
    unsigned a;
    asm("{ .reg .u64 t; cvta.to.shared.u64 t, %1; cvt.u32.u64 %0, t; }" : "=r"(a) : "l"(p));
    return a;
}
__device__ __forceinline__ float ex2f(float x) {
    float r;
    asm("ex2.approx.ftz.f32 %0, %1;" : "=f"(r) : "f"(x));
    return r;
}
#define MBAR_INIT(addr, cnt) \
    asm volatile("mbarrier.init.shared.b64 [%0], %1;" :: "r"(addr), "r"(cnt) : "memory")
#define MBAR_EXPECT_TX(addr, bytes) \
    asm volatile("mbarrier.arrive.expect_tx.shared.b64 _, [%0], %1;" :: "r"(addr), "r"(bytes) : "memory")
#define MBAR_ARRIVE(addr) \
    asm volatile("mbarrier.arrive.shared.b64 _, [%0];" :: "r"(addr) : "memory")
#define MBAR_WAIT(addr, ph) do { \
    unsigned _m = (addr), _p = (ph), _d; \
    asm volatile("{\n\t.reg .pred p;\n\tmbarrier.try_wait.parity.acquire.cta.shared::cta.b64 p, [%1], %2;\n\tselp.b32 %0, 1, 0, p;\n\t}" \
                 : "=r"(_d) : "r"(_m), "r"(_p) : "memory"); \
    if (!_d) { \
        asm volatile("{\n\t.reg .pred P1;\n\tWL%=:\n\tmbarrier.try_wait.parity.acquire.cta.shared::cta.b64 P1, [%0], %1, 0x989680;\n\t@P1 bra.uni WD%=;\n\tbra.uni WL%=;\n\tWD%=:\n\t}" \
                     :: "r"(_m), "r"(_p) : "memory"); \
    } } while (0)
#define BULK_G2S(dst, src, bytes, mbar) \
    asm volatile("cp.async.bulk.shared::cluster.global.mbarrier::complete_tx::bytes [%0], [%1], %2, [%3];" \
                 :: "r"(dst), "l"(src), "r"(bytes), "r"(mbar) : "memory")
#define LDSM4(r, addr) \
    asm volatile("ldmatrix.sync.aligned.m8n8.x4.shared.b16 {%0,%1,%2,%3}, [%4];" \
                 : "=r"((r)[0]), "=r"((r)[1]), "=r"((r)[2]), "=r"((r)[3]) : "r"(addr))
#define MMA_FP16(c, a, b0, b1) \
    asm volatile("mma.sync.aligned.m16n8k16.row.col.f32.f16.f16.f32 " \
                 "{%0,%1,%2,%3}, {%4,%5,%6,%7}, {%8,%9}, {%0,%1,%2,%3};" \
                 : "+f"((c)[0]), "+f"((c)[1]), "+f"((c)[2]), "+f"((c)[3]) \
                 : "r"((a)[0]), "r"((a)[1]), "r"((a)[2]), "r"((a)[3]), "r"(b0), "r"(b1))

__device__ __forceinline__ unsigned pack2(float a, float b) {
    __half2 h = __floats2half2_rn(a, b);   // a -> low half (lower address)
    return *(unsigned*)&h;
}

// ---------------- merged prep (unchanged from R10) ----------------
__global__ void prep_all(const float* __restrict__ f1, const float* __restrict__ f2,
                         const float* __restrict__ ul1, const float* __restrict__ ul2,
                         const int* __restrict__ sel1, const int* __restrict__ sel2,
                         const int* __restrict__ pl1, const int* __restrict__ pl2) {
    __shared__ float ws[8];
    const int t = threadIdx.x;
    const int r = t >> 6, sub = t & 63;
    const int kc2 = sub & 1, kh = (sub >> 1) & 1, kt = sub >> 2;
    const int k0 = kt * 16 + kh * 8 + kc2 * 4;

    if (blockIdx.x < 2016) {
        const int i = blockIdx.x * 4 + r;
        float4 x1 = make_float4(0.f, 0.f, 0.f, 0.f), x2 = x1;
        if (i < NROWS) {
            x1 = *(const float4*)(f1 + i * CDIM + k0);
            x2 = *(const float4*)(f2 + i * CDIM + k0);
        }
        const int tile = i >> 7, m = i & 127;
        const int mt = m >> 4, mi8 = (m >> 3) & 1, mr = m & 7;
        const int q = kh * 2 + mi8;
        const unsigned off = (unsigned)(((kt * 8 + mt) << 9) + (q << 7) + (mr << 4) + kc2 * 8);
        *(uint2*)(g_Asw[0] + (size_t)tile * ATILE_BYTES + off) =
            make_uint2(pack2(x1.x, x1.y), pack2(x1.z, x1.w));
        *(uint2*)(g_Asw[1] + (size_t)tile * ATILE_BYTES + off) =
            make_uint2(pack2(x2.x, x2.y), pack2(x2.z, x2.w));
        float p = x1.x * x2.x + x1.y * x2.y + x1.z * x2.z + x1.w * x2.w;
        #pragma unroll
        for (int o = 16; o > 0; o >>= 1) p += __shfl_xor_sync(0xffffffffu, p, o);
        if ((t & 31) == 0) ws[t >> 5] = p;
        __syncthreads();
        if (sub == 0 && i < NROWS)
            g_pos[i] = (ws[r * 2] + ws[r * 2 + 1]) * 10.f;
    } else {
        const int j = (blockIdx.x - 2016) * 4 + r;   // j < 8192
        float x0 = 0.f, xa = 0.f, xb = 0.f, xc = 0.f;
        if (j < NROWS) {
            int n; const float* ul; const int* pl;
            if (j < 4000) { n = sel1[j];        ul = ul1; pl = pl1; }
            else          { n = sel2[j - 4000]; ul = ul2; pl = pl2; }
            const int b = n / HW, hw = n - b * HW;
            const float* src = ul + (size_t)(b * CDIM + k0) * HW + hw;
            x0 = src[0]; xa = src[HW]; xb = src[2 * HW]; xc = src[3 * HW];
            if (sub == 0) g_memlab[j] = (float)pl[n];
        }
        if (sub == 1) {
            g_alf[0][j] = (j < NROWS) ? (float)pl1[j] : 0.f;
            g_alf[1][j] = (j < NROWS) ? (float)pl2[j] : 0.f;
        }
        const int chunk = j >> 7, nn = j & 127;
        const int nt = nn >> 4, ni8 = (nn >> 3) & 1, nr = nn & 7;
        const int q = ni8 * 2 + kh;
        const unsigned off = (unsigned)(((kt * 8 + nt) << 9) + (q << 7) + (nr << 4) + kc2 * 8);
        *(uint2*)(g_Bsw + (size_t)chunk * BSTAGE_BYTES + off) =
            make_uint2(pack2(x0, xa), pack2(xb, xc));
    }
}

// ---------------- fold one element of the PREVIOUS stage's scores ----------------
#define FOLD1(Cp, f, ps) do { \
    const int mi_ = (f) >> 4, nj_ = ((f) >> 2) & 3, e_ = (f) & 3; \
    const int rh_ = e_ >> 1; \
    float sv_ = Cp[mi_][nj_][e_]; \
    float lb_; \
    asm volatile("ld.shared.f32 %0, [%1];" : "=f"(lb_) \
        : "r"(sb + SM_LAB + (unsigned)(((unsigned)(ps) * 128u + wn * 32u + nj_ * 8u + ((lane & 3) << 1) + (e_ & 1)) << 2))); \
    rmx[mi_][rh_] = fmaxf(rmx[mi_][rh_], sv_); \
    float ex_ = ex2f(fmaf(sv_, K_EX2A, K_EX2B)); \
    tal[mi_][rh_] += ex_; \
    t1a[mi_][rh_] = fmaf(ex_, lb_, t1a[mi_][rh_]); \
    Cp[mi_][nj_][e_] = 0.f; \
} while (0)

// one step: prefetch next step's B (warp0 lane0) + 16 kt of MMA + interleaved fold
#define STAGE(tcur, sg, Ccur, Cprv, DOFOLD) do { \
    const int buf_ = (tcur) & 1; \
    if (wid == 0 && lane == 0) { \
        const int nt_ = (tcur) + 1; \
        if (nt_ < nsteps) { \
            if (nt_ >= 2) MBAR_WAIT(sb + SM_FREE + 16 * (nt_ & 1), ((nt_ - 2) >> 1) & 1); \
            MBAR_EXPECT_TX(sb + SM_FULL + 16 * (nt_ & 1), BSTAGE_BYTES); \
            const int sgn_ = (((jb + (nt_ >> 3)) & 7) << 3) + (nt_ & 7); \
            BULK_G2S(sb + SM_B + ((unsigned)(nt_ & 1) << 16), \
                     g_Bsw + (size_t)sgn_ * BSTAGE_BYTES, (unsigned)BSTAGE_BYTES, \
                     sb + SM_FULL + 16 * (nt_ & 1)); \
        } \
    } \
    MBAR_WAIT(sb + SM_FULL + 16 * buf_, ((tcur) >> 1) & 1); \
    const unsigned bbase_ = sb + SM_B + ((unsigned)buf_ << 16) + lanoff; \
    _Pragma("unroll") \
    for (int kt_ = 0; kt_ < 16; kt_++) { \
        unsigned Ar0[4], Ar1[4], Bf0[4], Bf1[4]; \
        LDSM4(Ar0, abase  + (unsigned)((kt_ * 8 + wm * 2 + 0) << 9)); \
        LDSM4(Ar1, abase  + (unsigned)((kt_ * 8 + wm * 2 + 1) << 9)); \
        LDSM4(Bf0, bbase_ + (unsigned)((kt_ * 8 + wn * 2 + 0) << 9)); \
        LDSM4(Bf1, bbase_ + (unsigned)((kt_ * 8 + wn * 2 + 1) << 9)); \
        MMA_FP16(Ccur[0][0], Ar0, Bf0[0], Bf0[1]); \
        MMA_FP16(Ccur[0][1], Ar0, Bf0[2], Bf0[3]); \
        MMA_FP16(Ccur[0][2], Ar0, Bf1[0], Bf1[1]); \
        MMA_FP16(Ccur[0][3], Ar0, Bf1[2], Bf1[3]); \
        MMA_FP16(Ccur[1][0], Ar1, Bf0[0], Bf0[1]); \
        MMA_FP16(Ccur[1][1], Ar1, Bf0[2], Bf0[3]); \
        MMA_FP16(Ccur[1][2], Ar1, Bf1[0], Bf1[1]); \
        MMA_FP16(Ccur[1][3], Ar1, Bf1[2], Bf1[3]); \
        if (DOFOLD) { \
            FOLD1(Cprv, kt_ * 2 + 0, (sg) - 1); \
            FOLD1(Cprv, kt_ * 2 + 1, (sg) - 1); \
        } \
    } \
    if (lane == 0) MBAR_ARRIVE(sb + SM_FREE + 16 * buf_); \
} while (0)

// ---------------- main: persistent 148-CTA GEMM over 1008 (anchor, mtile, chunk) jobs ----------------
__global__ __launch_bounds__(512, 1) void contrast_mm() {
    extern __shared__ char smem[];
    const unsigned sb = smem_u32(smem);
    const int tid = threadIdx.x, wid = tid >> 5, lane = tid & 31;
    const int c = blockIdx.x;
    const int jb = (c * NJOBS) / GRIDC, je = ((c + 1) * NJOBS) / GRIDC;
    const int nsteps = (je - jb) * 8;

    if (tid == 0) {
        MBAR_INIT(sb + SM_AF, 1);
        MBAR_INIT(sb + SM_FULL + 0, 1);   MBAR_INIT(sb + SM_FULL + 16, 1);
        MBAR_INIT(sb + SM_FREE + 0, 16);  MBAR_INIT(sb + SM_FREE + 16, 16);
    }
    __syncthreads();
    if (tid == 0) {   // prefetch B for step 0
        MBAR_EXPECT_TX(sb + SM_FULL + 0, BSTAGE_BYTES);
        BULK_G2S(sb + SM_B, g_Bsw + (size_t)((jb & 7) * 8) * BSTAGE_BYTES,
                 (unsigned)BSTAGE_BYTES, sb + SM_FULL + 0);
    }

    const int wm = wid >> 2, wn = wid & 3;   // 4 M-warps x 4 N-warps, tile 32x32
    const unsigned lanoff = (unsigned)(((lane >> 3) << 7) + ((lane & 7) << 4));
    const unsigned abase = sb + SM_A + lanoff;

    float Ca[2][4][4], Cb[2][4][4];
    #pragma unroll
    for (int mi = 0; mi < 2; mi++)
        #pragma unroll
        for (int nj = 0; nj < 4; nj++)
            #pragma unroll
            for (int e = 0; e < 4; e++) { Ca[mi][nj][e] = 0.f; Cb[mi][nj][e] = 0.f; }
    float rmx[2][2], tal[2][2], t1a[2][2];
    #pragma unroll
    for (int mi = 0; mi < 2; mi++)
        #pragma unroll
        for (int rh = 0; rh < 2; rh++) { rmx[mi][rh] = -1e30f; tal[mi][rh] = 0.f; t1a[mi][rh] = 0.f; }

    int aphase = 0, cur_a = -1, cur_mt = -1, t = 0;

    for (int j = jb; j < je; j++) {
        const int a = j / 504, mt = (j % 504) >> 3, ch = j & 7;
        if (a != cur_a || mt != cur_mt) {
            __syncthreads();   // all warps done with old A tile
            if (tid == 0) {
                const unsigned bytes = (unsigned)ATILE_BYTES + (a != cur_a ? (unsigned)LAB_BYTES : 0u);
                MBAR_EXPECT_TX(sb + SM_AF, bytes);
                BULK_G2S(sb + SM_A, g_Asw[a] + (size_t)mt * ATILE_BYTES,
                         (unsigned)ATILE_BYTES, sb + SM_AF);
                if (a != cur_a)
                    BULK_G2S(sb + SM_LAB, g_alf[a], (unsigned)LAB_BYTES, sb + SM_AF);
            }
            MBAR_WAIT(sb + SM_AF, aphase);
            aphase ^= 1;
            cur_a = a; cur_mt = mt;
        }
        const int sg0 = ch * 8;
        for (int sp = 0; sp < 4; sp++) {
            const bool f0 = (sp > 0);
            STAGE(t,     sg0 + sp * 2,     Ca, Cb, f0);
            STAGE(t + 1, sg0 + sp * 2 + 1, Cb, Ca, true);
            t += 2;
        }
        #pragma unroll
        for (int f = 0; f < 32; f++) FOLD1(Cb, f, sg0 + 7);   // fold final stage of job

        // flush per-job partials: quad reduce then write (job, wn, row) slots
        #pragma unroll
        for (int mi = 0; mi < 2; mi++)
            #pragma unroll
            for (int rh = 0; rh < 2; rh++) {
                #pragma unroll
                for (int off = 1; off <= 2; off <<= 1) {
                    rmx[mi][rh] = fmaxf(rmx[mi][rh], __shfl_xor_sync(0xffffffffu, rmx[mi][rh], off));
                    tal[mi][rh] += __shfl_xor_sync(0xffffffffu, tal[mi][rh], off);
                    t1a[mi][rh] += __shfl_xor_sync(0xffffffffu, t1a[mi][rh], off);
                }
            }
        if ((lane & 3) == 0) {
            #pragma unroll
            for (int mi = 0; mi < 2; mi++)
                #pragma unroll
                for (int rh = 0; rh < 2; rh++) {
                    const int rr = wm * 32 + mi * 16 + rh * 8 + (lane >> 2);
                    g_jpart[((size_t)j * 4 + wn) * 128 + rr] =
                        make_float4(rmx[mi][rh], tal[mi][rh], t1a[mi][rh], 0.f);
                }
        }
        #pragma unroll
        for (int mi = 0; mi < 2; mi++)
            #pragma unroll
            for (int rh = 0; rh < 2; rh++) { rmx[mi][rh] = -1e30f; tal[mi][rh] = 0.f; t1a[mi][rh] = 0.f; }
    }
}

// ---------------- combine: reduce job partials -> per-row loss -> masked tile partials ----------------
__global__ void combine(const float* __restrict__ plog1, const float* __restrict__ plog2) {
    __shared__ float sm[4][2];
    const int x = blockIdx.x;            // 0..125
    const int a = x / MTILES, mt = x % MTILES;
    const int row = threadIdx.x;         // 128
    const int lane = row & 31;

    float rmax = -1e30f, tall = 0.f, t1v = 0.f;
    const size_t jbase = ((size_t)a * 504 + (size_t)mt * 8) * 4 * 128;
    #pragma unroll
    for (int ch = 0; ch < 8; ch++)
        #pragma unroll
        for (int wn = 0; wn < 4; wn++) {
            float4 v = g_jpart[jbase + ((size_t)ch * 4 + wn) * 128 + row];
            rmax = fmaxf(rmax, v.x);
            tall += v.y;
            t1v  += v.z;
        }
    tall -= (float)(NPADN - NROWS) * ex2f(K_EX2B);   // remove padded-column contributions

    float num = 0.f, cnt = 0.f;
    const int i = mt * MT + row;
    if (i < NROWS) {
        float posv = g_pos[i];
        float mfull = fmaxf(rmax * 10.f, posv);
        float tsel = (g_memlab[i] == 0.f) ? t1v : (tall - t1v);
        float epos = __expf(posv - mfull);
        float sum = epos + tsel * __expf(12.f - mfull);
        float lossv = -logf(epos / (sum + 1e-8f) + 1e-8f);
        float q1 = plog1[i], q2 = plog2[i];
        float mask = a ? ((q1 > 0.7f && q2 < q1) ? 1.f : 0.f)
                       : ((q2 > 0.7f && q1 < q2) ? 1.f : 0.f);
        num = lossv * mask;
        cnt = mask;
    }
    #pragma unroll
    for (int o = 16; o > 0; o >>= 1) {
        num += __shfl_xor_sync(0xffffffffu, num, o);
        cnt += __shfl_xor_sync(0xffffffffu, cnt, o);
    }
    if (lane == 0) { sm[row >> 5][0] = num; sm[row >> 5][1] = cnt; }
    __syncthreads();
    if (row == 0) {
        float n = sm[0][0] + sm[1][0] + sm[2][0] + sm[3][0];
        float cc = sm[0][1] + sm[1][1] + sm[2][1] + sm[3][1];
        g_part[a][mt] = make_float2(n, cc);
    }
}

// ---------------- tiny deterministic final reduction ----------------
__global__ void finalize(float* __restrict__ out) {
    __shared__ float sm[4][2];
    const int t = threadIdx.x;                 // 128 threads
    const int a = t >> 6, idx = t & 63;
    float n = 0.f, c = 0.f;
    if (idx < MTILES) { float2 v = g_part[a][idx]; n = v.x; c = v.y; }
    #pragma unroll
    for (int o = 16; o > 0; o >>= 1) {
        n += __shfl_xor_sync(0xffffffffu, n, o);
        c += __shfl_xor_sync(0xffffffffu, c, o);
    }
    if ((t & 31) == 0) { sm[t >> 5][0] = n; sm[t >> 5][1] = c; }
    __syncthreads();
    if (t == 0) {
        float n1 = sm[0][0] + sm[1][0], c1 = sm[0][1] + sm[1][1];
        float n2 = sm[2][0] + sm[3][0], c2 = sm[2][1] + sm[3][1];
        out[0] = n1 / (c1 + 1e-12f) + n2 / (c2 + 1e-12f);
    }
}

// ---------------- launch ----------------
extern "C" void kernel_launch(void* const* d_in, const int* in_sizes, int n_in,
                              void* d_out, int out_size) {
    const float* feat1 = (const float*)d_in[0];
    const float* feat2 = (const float*)d_in[1];
    const float* ul1   = (const float*)d_in[2];
    const float* ul2   = (const float*)d_in[3];
    const int*   pl1   = (const int*)d_in[4];
    const int*   pl2   = (const int*)d_in[5];
    const float* plog1 = (const float*)d_in[6];
    const float* plog2 = (const float*)d_in[7];
    const int*   sel1  = (const int*)d_in[8];
    const int*   sel2  = (const int*)d_in[9];
    float* out = (float*)d_out;

    cudaFuncSetAttribute(contrast_mm, cudaFuncAttributeMaxDynamicSharedMemorySize, SMEM_TOTAL);

    prep_all<<<4064, 256>>>(feat1, feat2, ul1, ul2, sel1, sel2, pl1, pl2);
    contrast_mm<<<GRIDC, 512, SMEM_TOTAL>>>();
    combine<<<2 * MTILES, 128>>>(plog1, plog2);
    finalize<<<1, 128>>>(out);
}